// round 1
// baseline (speedup 1.0000x reference)
#include <cuda_runtime.h>
#include <math.h>
#include <stdint.h>

// Problem constants
#define BSZ 2
#define SEQ 2048
#define DM  896
#define NL  24
#define NHQ 14
#define NHKV 2
#define DH  64
#define IFF 4864
#define ROWS (BSZ*SEQ)          // 4096
#define QKD (NHQ*DH)            // 896
#define KVD (NHKV*DH)           // 128

// ---------------- scratch (device globals; no allocations allowed) ----------
__device__ float g_x [ROWS*DM];
__device__ float g_h [ROWS*DM];
__device__ float g_q [ROWS*QKD];
__device__ float g_k [ROWS*KVD];
__device__ float g_v [ROWS*KVD];
__device__ float g_ao[ROWS*QKD];
__device__ float g_gate[(size_t)ROWS*IFF];
__device__ float g_up  [(size_t)ROWS*IFF];

// ---------------- elementwise copy ----------------
__global__ void copy_k(float* __restrict__ dst, const float* __restrict__ src, int n) {
    int i = blockIdx.x * blockDim.x + threadIdx.x;
    if (i < n) dst[i] = src[i];
}

// ---------------- RMSNorm: one block per row ----------------
__global__ __launch_bounds__(256) void rmsnorm_k(const float* __restrict__ x,
                                                 const float* __restrict__ w,
                                                 float* __restrict__ o) {
    int row = blockIdx.x;
    const float* xr = x + (size_t)row * DM;
    float s = 0.f;
    for (int i = threadIdx.x; i < DM; i += 256) { float v = xr[i]; s += v * v; }
    __shared__ float red[256];
    red[threadIdx.x] = s;
    __syncthreads();
    for (int st = 128; st > 0; st >>= 1) {
        if (threadIdx.x < st) red[threadIdx.x] += red[threadIdx.x + st];
        __syncthreads();
    }
    float r = rsqrtf(red[0] / (float)DM + 1e-6f);
    float* orow = o + (size_t)row * DM;
    for (int i = threadIdx.x; i < DM; i += 256) orow[i] = xr[i] * r * w[i];
}

// ---------------- SGEMM: C[M,N] = A[M,K] @ W[K,N] (+epilogue) ----------------
// EPI 0: C = acc + bias (bias may be null)
// EPI 1: C += acc
// EPI 2: C = silu(G) * acc   (G same shape as C)
// Assumes M%64==0, N%64==0, K%16==0 (true for all shapes here).
template <int EPI>
__global__ __launch_bounds__(256) void sgemm_k(const float* __restrict__ A,
                                               const float* __restrict__ W,
                                               const float* __restrict__ bias,
                                               const float* __restrict__ G,
                                               float* __restrict__ C,
                                               int M, int N, int K) {
    __shared__ float As[16][68];
    __shared__ float Bs[16][64];
    int tid = threadIdx.x;
    int tx = tid & 15, ty = tid >> 4;
    int row0 = blockIdx.y * 64, col0 = blockIdx.x * 64;

    float acc[4][4] = {};
    int ac = tid & 15, ar = tid >> 4;   // A-load: col within BK, row base
    int br = tid >> 6, bc = tid & 63;   // B-load

    for (int k0 = 0; k0 < K; k0 += 16) {
#pragma unroll
        for (int i = 0; i < 4; i++)
            As[ac][ar + i * 16] = A[(size_t)(row0 + ar + i * 16) * K + k0 + ac];
#pragma unroll
        for (int i = 0; i < 4; i++)
            Bs[br + i * 4][bc] = W[(size_t)(k0 + br + i * 4) * N + col0 + bc];
        __syncthreads();
#pragma unroll
        for (int kk = 0; kk < 16; kk++) {
            float a[4], b[4];
#pragma unroll
            for (int i = 0; i < 4; i++) a[i] = As[kk][ty * 4 + i];
#pragma unroll
            for (int j = 0; j < 4; j++) b[j] = Bs[kk][tx * 4 + j];
#pragma unroll
            for (int i = 0; i < 4; i++)
#pragma unroll
                for (int j = 0; j < 4; j++) acc[i][j] += a[i] * b[j];
        }
        __syncthreads();
    }

#pragma unroll
    for (int i = 0; i < 4; i++) {
        int r = row0 + ty * 4 + i;
#pragma unroll
        for (int j = 0; j < 4; j++) {
            int c = col0 + tx * 4 + j;
            size_t idx = (size_t)r * N + c;
            if (EPI == 0) {
                float bval = bias ? bias[c] : 0.f;
                C[idx] = acc[i][j] + bval;
            } else if (EPI == 1) {
                C[idx] += acc[i][j];
            } else {
                float g = G[idx];
                C[idx] = acc[i][j] * (g / (1.f + expf(-g)));
            }
        }
    }
}

// ---------------- RoPE (in place): one block per (b,s); H*32 threads --------
__global__ void rope_k(float* __restrict__ p, int H) {
    int row = blockIdx.x;          // b*SEQ + s
    int s = row & (SEQ - 1);
    int t = threadIdx.x;
    int h = t >> 5, i = t & 31;
    float inv = 1.0f / powf(1.0e6f, (float)i / 32.0f);
    float ang = (float)s * inv;
    float c = cosf(ang), sn = sinf(ang);
    float* base = p + ((size_t)row * H + h) * DH;
    float x1 = base[i], x2 = base[i + 32];
    base[i]      = x1 * c - x2 * sn;
    base[i + 32] = x2 * c + x1 * sn;
}

// ---------------- Attention: flash-style, 4 queries per block ----------------
// grid (SEQ/4, NHQ, BSZ), 128 threads (warp = one query row)
__global__ __launch_bounds__(128) void attn_k(const float* __restrict__ q,
                                              const float* __restrict__ k,
                                              const float* __restrict__ v,
                                              const int* __restrict__ tt,
                                              const float* __restrict__ am,
                                              float* __restrict__ out) {
    __shared__ float Ks[64][65];
    __shared__ float Vs[64][65];
    __shared__ float qs[4][64];
    __shared__ float ps[4][64];
    __shared__ int   tts[64];
    __shared__ float ms[64];

    int b = blockIdx.z, h = blockIdx.y;
    int w = threadIdx.x >> 5;
    int lane = threadIdx.x & 31;
    int qi = blockIdx.x * 4 + w;
    int kvh = h / (NHQ / NHKV);

    const float* qr = q + ((size_t)(b * SEQ + qi) * NHQ + h) * DH;
    qs[w][lane]      = qr[lane];
    qs[w][lane + 32] = qr[lane + 32];
    int tq = tt[b * SEQ + qi];

    float m = -INFINITY, l = 0.f, o0 = 0.f, o1 = 0.f;
    const float scale = 0.125f;       // 1/sqrt(64)
    const float NEG = -3.0e38f;
    int j1 = lane, j2 = lane + 32;

    for (int kt = 0; kt < SEQ; kt += 64) {
        __syncthreads();
        for (int idx = threadIdx.x; idx < 64 * 64; idx += 128) {
            int r = idx >> 6, d = idx & 63;
            size_t gi = ((size_t)(b * SEQ + kt + r) * NHKV + kvh) * DH + d;
            Ks[r][d] = k[gi];
            Vs[r][d] = v[gi];
        }
        if (threadIdx.x < 64) {
            tts[threadIdx.x] = tt[b * SEQ + kt + threadIdx.x];
            ms[threadIdx.x]  = am[b * SEQ + kt + threadIdx.x];
        }
        __syncthreads();

        float s1 = 0.f, s2 = 0.f;
#pragma unroll 8
        for (int d = 0; d < DH; d++) {
            float qd = qs[w][d];
            s1 += qd * Ks[j1][d];
            s2 += qd * Ks[j2][d];
        }
        // bias: allowed = (tq==0 & tk==0) | (tq==1 & (tk==0 | (tk==1 & ki<=qi)))
        {
            int tk = tts[j1], ki = kt + j1;
            bool allowed = (tq == 0) ? (tk == 0) : ((tk == 0) || (ki <= qi));
            s1 = s1 * scale + (allowed ? 0.f : NEG) + (1.f - ms[j1]) * NEG;
            s1 = fmaxf(s1, -3.3e38f);
        }
        {
            int tk = tts[j2], ki = kt + j2;
            bool allowed = (tq == 0) ? (tk == 0) : ((tk == 0) || (ki <= qi));
            s2 = s2 * scale + (allowed ? 0.f : NEG) + (1.f - ms[j2]) * NEG;
            s2 = fmaxf(s2, -3.3e38f);
        }

        float tm = fmaxf(s1, s2);
#pragma unroll
        for (int o = 16; o; o >>= 1) tm = fmaxf(tm, __shfl_xor_sync(0xffffffffu, tm, o));
        float mn = fmaxf(m, tm);
        float corr = expf(m - mn);              // m=-inf on first tile -> 0 (mn finite)
        float p1 = expf(s1 - mn), p2 = expf(s2 - mn);
        ps[w][j1] = p1; ps[w][j2] = p2;
        float psum = p1 + p2;
#pragma unroll
        for (int o = 16; o; o >>= 1) psum += __shfl_xor_sync(0xffffffffu, psum, o);
        l = l * corr + psum;
        o0 *= corr; o1 *= corr;
        m = mn;
        __syncwarp();
#pragma unroll 8
        for (int j = 0; j < 64; j++) {
            float pj = ps[w][j];
            o0 += pj * Vs[j][j1];
            o1 += pj * Vs[j][j2];
        }
    }

    float invl = 1.0f / l;
    float* orow = out + ((size_t)(b * SEQ + qi) * NHQ + h) * DH;
    orow[j1] = o0 * invl;
    orow[j2] = o1 * invl;
}

// ---------------- host driver ----------------
extern "C" void kernel_launch(void* const* d_in, const int* in_sizes, int n_in,
                              void* d_out, int out_size) {
    const float* emb = (const float*)d_in[0];
    const int*   tt  = (const int*)  d_in[1];
    const float* am  = (const float*)d_in[2];
    const float* wq  = (const float*)d_in[3];
    const float* bq  = (const float*)d_in[4];
    const float* wk  = (const float*)d_in[5];
    const float* bk  = (const float*)d_in[6];
    const float* wv  = (const float*)d_in[7];
    const float* bv  = (const float*)d_in[8];
    const float* wo  = (const float*)d_in[9];
    const float* wg  = (const float*)d_in[10];
    const float* wu  = (const float*)d_in[11];
    const float* wd  = (const float*)d_in[12];
    const float* ln1 = (const float*)d_in[13];
    const float* ln2 = (const float*)d_in[14];
    const float* lnf = (const float*)d_in[15];

    float *x, *h, *q, *k, *v, *ao, *gt, *up;
    cudaGetSymbolAddress((void**)&x,  g_x);
    cudaGetSymbolAddress((void**)&h,  g_h);
    cudaGetSymbolAddress((void**)&q,  g_q);
    cudaGetSymbolAddress((void**)&k,  g_k);
    cudaGetSymbolAddress((void**)&v,  g_v);
    cudaGetSymbolAddress((void**)&ao, g_ao);
    cudaGetSymbolAddress((void**)&gt, g_gate);
    cudaGetSymbolAddress((void**)&up, g_up);

    int nx = ROWS * DM;
    copy_k<<<(nx + 255) / 256, 256>>>(x, emb, nx);

    dim3 gQK (QKD / 64, ROWS / 64);   // (14, 64)
    dim3 gKV (KVD / 64, ROWS / 64);   // (2, 64)
    dim3 gFF (IFF / 64, ROWS / 64);   // (76, 64)
    dim3 gAt (SEQ / 4, NHQ, BSZ);

    for (int l = 0; l < NL; l++) {
        rmsnorm_k<<<ROWS, 256>>>(x, ln1 + (size_t)l * DM, h);

        sgemm_k<0><<<gQK, 256>>>(h, wq + (size_t)l * DM * QKD, bq + (size_t)l * QKD,
                                 nullptr, q, ROWS, QKD, DM);
        sgemm_k<0><<<gKV, 256>>>(h, wk + (size_t)l * DM * KVD, bk + (size_t)l * KVD,
                                 nullptr, k, ROWS, KVD, DM);
        sgemm_k<0><<<gKV, 256>>>(h, wv + (size_t)l * DM * KVD, bv + (size_t)l * KVD,
                                 nullptr, v, ROWS, KVD, DM);

        rope_k<<<ROWS, NHQ * 32>>>(q, NHQ);
        rope_k<<<ROWS, NHKV * 32>>>(k, NHKV);

        attn_k<<<gAt, 128>>>(q, k, v, tt, am, ao);

        sgemm_k<1><<<gQK, 256>>>(ao, wo + (size_t)l * QKD * DM, nullptr, nullptr,
                                 x, ROWS, DM, QKD);

        rmsnorm_k<<<ROWS, 256>>>(x, ln2 + (size_t)l * DM, h);

        sgemm_k<0><<<gFF, 256>>>(h, wg + (size_t)l * DM * IFF, nullptr, nullptr,
                                 gt, ROWS, IFF, DM);
        sgemm_k<2><<<gFF, 256>>>(h, wu + (size_t)l * DM * IFF, nullptr, gt,
                                 up, ROWS, IFF, DM);
        sgemm_k<1><<<gQK, 256>>>(up, wd + (size_t)l * IFF * DM, nullptr, nullptr,
                                 x, ROWS, DM, IFF);
    }

    rmsnorm_k<<<ROWS, 256>>>(x, lnf, (float*)d_out);
}

// round 3
// speedup vs baseline: 2.4750x; 2.4750x over previous
#include <cuda_runtime.h>
#include <math.h>
#include <stdint.h>

// Problem constants
#define BSZ 2
#define SEQ 2048
#define DM  896
#define NL  24
#define NHQ 14
#define NHKV 2
#define DH  64
#define IFF 4864
#define ROWS (BSZ*SEQ)          // 4096
#define QKD (NHQ*DH)            // 896
#define KVD (NHKV*DH)           // 128

// ---------------- scratch (device globals; no allocations allowed) ----------
__device__ float g_x [ROWS*DM];
__device__ float g_h [ROWS*DM];
__device__ float g_q [ROWS*QKD];
__device__ float g_k [ROWS*KVD];
__device__ float g_v [ROWS*KVD];
__device__ float g_ao[ROWS*QKD];
__device__ float g_gate[(size_t)ROWS*IFF];
__device__ float g_up  [(size_t)ROWS*IFF];
// transposed weights (K-major B operands)
__device__ float g_wqT[(size_t)NL*QKD*DM];
__device__ float g_wkT[(size_t)NL*KVD*DM];
__device__ float g_wvT[(size_t)NL*KVD*DM];
__device__ float g_woT[(size_t)NL*DM*QKD];
__device__ float g_wgT[(size_t)NL*IFF*DM];
__device__ float g_wuT[(size_t)NL*IFF*DM];
__device__ float g_wdT[(size_t)NL*DM*IFF];

// ---------------- PTX helpers ----------------
__device__ __forceinline__ uint32_t smem_u32(const void* p) {
    uint32_t a;
    asm("{ .reg .u64 t; cvta.to.shared.u64 t, %1; cvt.u32.u64 %0, t; }" : "=r"(a) : "l"(p));
    return a;
}
__device__ __forceinline__ void cp_async16(uint32_t s, const void* g) {
    asm volatile("cp.async.cg.shared.global [%0], [%1], 16;\n" :: "r"(s), "l"(g));
}
__device__ __forceinline__ void cp_commit() { asm volatile("cp.async.commit_group;\n" ::: "memory"); }
template <int N>
__device__ __forceinline__ void cp_wait() { asm volatile("cp.async.wait_group %0;\n" :: "n"(N) : "memory"); }

__device__ __forceinline__ uint32_t f2tf(float x) {
    uint32_t r;
    asm("cvt.rna.tf32.f32 %0, %1;" : "=r"(r) : "f"(x));
    return r;
}
__device__ __forceinline__ void mma8(float* c, const uint32_t* a, const uint32_t* b) {
    asm volatile(
        "mma.sync.aligned.m16n8k8.row.col.f32.tf32.tf32.f32 "
        "{%0,%1,%2,%3}, {%4,%5,%6,%7}, {%8,%9}, {%0,%1,%2,%3};"
        : "+f"(c[0]), "+f"(c[1]), "+f"(c[2]), "+f"(c[3])
        : "r"(a[0]), "r"(a[1]), "r"(a[2]), "r"(a[3]), "r"(b[0]), "r"(b[1]));
}

// ---------------- elementwise copy ----------------
__global__ void copy_k(float* __restrict__ dst, const float* __restrict__ src, int n) {
    int i = blockIdx.x * blockDim.x + threadIdx.x;
    if (i < n) dst[i] = src[i];
}

// ---------------- transpose: out[c][r] = in[r][c], per-layer (z) ------------
__global__ __launch_bounds__(256) void transpose_k(const float* __restrict__ in,
                                                   float* __restrict__ out,
                                                   int R, int C) {
    __shared__ float t[32][33];
    size_t lo = (size_t)blockIdx.z * R * C;
    const float* ip = in + lo;
    float* op = out + lo;
    int r0 = blockIdx.y * 32, c0 = blockIdx.x * 32;
    int tx = threadIdx.x & 31, ty = threadIdx.x >> 5;
#pragma unroll
    for (int i = 0; i < 32; i += 8)
        t[ty + i][tx] = ip[(size_t)(r0 + ty + i) * C + c0 + tx];
    __syncthreads();
#pragma unroll
    for (int i = 0; i < 32; i += 8)
        op[(size_t)(c0 + ty + i) * R + r0 + tx] = t[tx][ty + i];
}

// ---------------- RMSNorm ----------------
__global__ __launch_bounds__(256) void rmsnorm_k(const float* __restrict__ x,
                                                 const float* __restrict__ w,
                                                 float* __restrict__ o) {
    int row = blockIdx.x;
    const float* xr = x + (size_t)row * DM;
    float s = 0.f;
    for (int i = threadIdx.x; i < DM; i += 256) { float v = xr[i]; s += v * v; }
    __shared__ float red[256];
    red[threadIdx.x] = s;
    __syncthreads();
    for (int st = 128; st > 0; st >>= 1) {
        if (threadIdx.x < st) red[threadIdx.x] += red[threadIdx.x + st];
        __syncthreads();
    }
    float r = rsqrtf(red[0] / (float)DM + 1e-6f);
    float* orow = o + (size_t)row * DM;
    for (int i = threadIdx.x; i < DM; i += 256) orow[i] = xr[i] * r * w[i];
}

// ---------------- mma.sync tf32 GEMM: C[M,N] = A[M,K] @ Bt[N,K]^T ------------
// CTA tile 128x128, BK=16, 8 warps (2x4), warp tile 64x32, 2-stage cp.async.
// EPI 0: C = acc + bias (bias may be null)
// EPI 1: C += acc
// EPI 2: C = silu(G) * acc
// Requires M%128==0, N%128==0, K%16==0.
#define SPITCH 20
template <int EPI>
__global__ __launch_bounds__(256) void mgemm_k(const float* __restrict__ A,
                                               const float* __restrict__ Bt,
                                               const float* __restrict__ bias,
                                               const float* __restrict__ G,
                                               float* __restrict__ C,
                                               int M, int N, int K) {
    __shared__ float As[2][128 * SPITCH];
    __shared__ float Bs[2][128 * SPITCH];

    int tid = threadIdx.x;
    int wid = tid >> 5;
    int lane = tid & 31;
    int gid = lane >> 2, t4 = lane & 3;
    int wm = wid & 1, wn = wid >> 1;
    int row0 = blockIdx.y * 128, col0 = blockIdx.x * 128;

    uint32_t sA[2] = { smem_u32(&As[0][0]), smem_u32(&As[1][0]) };
    uint32_t sB[2] = { smem_u32(&Bs[0][0]), smem_u32(&Bs[1][0]) };

    const int NK = K >> 4;
    float acc[4][4][4] = {};

    // prologue: stage 0
    {
#pragma unroll
        for (int i = 0; i < 2; i++) {
            int c = tid + (i << 8);
            int r = c >> 2, cv = c & 3;
            uint32_t off = (uint32_t)(r * SPITCH + cv * 4) * 4;
            cp_async16(sA[0] + off, A  + (size_t)(row0 + r) * K + cv * 4);
            cp_async16(sB[0] + off, Bt + (size_t)(col0 + r) * K + cv * 4);
        }
        cp_commit();
    }

    for (int kt = 0; kt < NK; kt++) {
        int s = kt & 1;
        if (kt + 1 < NK) {
            int so = s ^ 1;
            int k0 = (kt + 1) << 4;
#pragma unroll
            for (int i = 0; i < 2; i++) {
                int c = tid + (i << 8);
                int r = c >> 2, cv = c & 3;
                uint32_t off = (uint32_t)(r * SPITCH + cv * 4) * 4;
                cp_async16(sA[so] + off, A  + (size_t)(row0 + r) * K + k0 + cv * 4);
                cp_async16(sB[so] + off, Bt + (size_t)(col0 + r) * K + k0 + cv * 4);
            }
            cp_commit();
            cp_wait<1>();
        } else {
            cp_wait<0>();
        }
        __syncthreads();

        const float* as = &As[s][0];
        const float* bs = &Bs[s][0];
#pragma unroll
        for (int ks = 0; ks < 2; ks++) {
            uint32_t af[4][4];
#pragma unroll
            for (int mt = 0; mt < 4; mt++) {
                int row = wm * 64 + mt * 16 + gid;
                int kc = ks * 8 + t4;
                af[mt][0] = f2tf(as[row * SPITCH + kc]);
                af[mt][1] = f2tf(as[(row + 8) * SPITCH + kc]);
                af[mt][2] = f2tf(as[row * SPITCH + kc + 4]);
                af[mt][3] = f2tf(as[(row + 8) * SPITCH + kc + 4]);
            }
            uint32_t bf[4][2];
#pragma unroll
            for (int nt = 0; nt < 4; nt++) {
                int col = wn * 32 + nt * 8 + gid;
                int kc = ks * 8 + t4;
                bf[nt][0] = f2tf(bs[col * SPITCH + kc]);
                bf[nt][1] = f2tf(bs[col * SPITCH + kc + 4]);
            }
#pragma unroll
            for (int mt = 0; mt < 4; mt++)
#pragma unroll
                for (int nt = 0; nt < 4; nt++)
                    mma8(acc[mt][nt], af[mt], bf[nt]);
        }
        __syncthreads();
    }

    // epilogue
#pragma unroll
    for (int mt = 0; mt < 4; mt++) {
#pragma unroll
        for (int nt = 0; nt < 4; nt++) {
            int rg = row0 + wm * 64 + mt * 16 + gid;
            int cg = col0 + wn * 32 + nt * 8 + 2 * t4;
#pragma unroll
            for (int half = 0; half < 2; half++) {
                int r = rg + half * 8;
                float v0 = acc[mt][nt][half * 2 + 0];
                float v1 = acc[mt][nt][half * 2 + 1];
                size_t idx = (size_t)r * N + cg;
                if (EPI == 0) {
                    float b0 = bias ? bias[cg] : 0.f;
                    float b1 = bias ? bias[cg + 1] : 0.f;
                    float2 o = make_float2(v0 + b0, v1 + b1);
                    *(float2*)(C + idx) = o;
                } else if (EPI == 1) {
                    float2 o = *(float2*)(C + idx);
                    o.x += v0; o.y += v1;
                    *(float2*)(C + idx) = o;
                } else {
                    float g0 = G[idx], g1 = G[idx + 1];
                    float2 o = make_float2(v0 * (g0 / (1.f + expf(-g0))),
                                           v1 * (g1 / (1.f + expf(-g1))));
                    *(float2*)(C + idx) = o;
                }
            }
        }
    }
}

// ---------------- RoPE (in place) ----------------
__global__ void rope_k(float* __restrict__ p, int H) {
    int row = blockIdx.x;
    int s = row & (SEQ - 1);
    int t = threadIdx.x;
    int h = t >> 5, i = t & 31;
    float inv = 1.0f / powf(1.0e6f, (float)i / 32.0f);
    float ang = (float)s * inv;
    float c = cosf(ang), sn = sinf(ang);
    float* base = p + ((size_t)row * H + h) * DH;
    float x1 = base[i], x2 = base[i + 32];
    base[i]      = x1 * c - x2 * sn;
    base[i + 32] = x2 * c + x1 * sn;
}

// ---------------- Attention: flash-style, 4 queries per block ----------------
__global__ __launch_bounds__(128) void attn_k(const float* __restrict__ q,
                                              const float* __restrict__ k,
                                              const float* __restrict__ v,
                                              const int* __restrict__ tt,
                                              const float* __restrict__ am,
                                              float* __restrict__ out) {
    __shared__ float Ks[64][65];
    __shared__ float Vs[64][65];
    __shared__ float qs[4][64];
    __shared__ float ps[4][64];
    __shared__ int   tts[64];
    __shared__ float ms[64];

    int b = blockIdx.z, h = blockIdx.y;
    int w = threadIdx.x >> 5;
    int lane = threadIdx.x & 31;
    int qi = blockIdx.x * 4 + w;
    int kvh = h / (NHQ / NHKV);

    const float* qr = q + ((size_t)(b * SEQ + qi) * NHQ + h) * DH;
    qs[w][lane]      = qr[lane];
    qs[w][lane + 32] = qr[lane + 32];
    int tq = tt[b * SEQ + qi];

    float m = -INFINITY, l = 0.f, o0 = 0.f, o1 = 0.f;
    const float scale = 0.125f;
    const float NEG = -3.0e38f;
    int j1 = lane, j2 = lane + 32;

    for (int kt = 0; kt < SEQ; kt += 64) {
        __syncthreads();
        for (int idx = threadIdx.x; idx < 64 * 64; idx += 128) {
            int r = idx >> 6, d = idx & 63;
            size_t gi = ((size_t)(b * SEQ + kt + r) * NHKV + kvh) * DH + d;
            Ks[r][d] = k[gi];
            Vs[r][d] = v[gi];
        }
        if (threadIdx.x < 64) {
            tts[threadIdx.x] = tt[b * SEQ + kt + threadIdx.x];
            ms[threadIdx.x]  = am[b * SEQ + kt + threadIdx.x];
        }
        __syncthreads();

        float s1 = 0.f, s2 = 0.f;
#pragma unroll 8
        for (int d = 0; d < DH; d++) {
            float qd = qs[w][d];
            s1 += qd * Ks[j1][d];
            s2 += qd * Ks[j2][d];
        }
        {
            int tk = tts[j1], ki = kt + j1;
            bool allowed = (tq == 0) ? (tk == 0) : ((tk == 0) || (ki <= qi));
            s1 = s1 * scale + (allowed ? 0.f : NEG) + (1.f - ms[j1]) * NEG;
            s1 = fmaxf(s1, -3.3e38f);
        }
        {
            int tk = tts[j2], ki = kt + j2;
            bool allowed = (tq == 0) ? (tk == 0) : ((tk == 0) || (ki <= qi));
            s2 = s2 * scale + (allowed ? 0.f : NEG) + (1.f - ms[j2]) * NEG;
            s2 = fmaxf(s2, -3.3e38f);
        }

        float tm = fmaxf(s1, s2);
#pragma unroll
        for (int o = 16; o; o >>= 1) tm = fmaxf(tm, __shfl_xor_sync(0xffffffffu, tm, o));
        float mn = fmaxf(m, tm);
        float corr = expf(m - mn);
        float p1 = expf(s1 - mn), p2 = expf(s2 - mn);
        ps[w][j1] = p1; ps[w][j2] = p2;
        float psum = p1 + p2;
#pragma unroll
        for (int o = 16; o; o >>= 1) psum += __shfl_xor_sync(0xffffffffu, psum, o);
        l = l * corr + psum;
        o0 *= corr; o1 *= corr;
        m = mn;
        __syncwarp();
#pragma unroll 8
        for (int j = 0; j < 64; j++) {
            float pj = ps[w][j];
            o0 += pj * Vs[j][j1];
            o1 += pj * Vs[j][j2];
        }
    }

    float invl = 1.0f / l;
    float* orow = out + ((size_t)(b * SEQ + qi) * NHQ + h) * DH;
    orow[j1] = o0 * invl;
    orow[j2] = o1 * invl;
}

// ---------------- host driver ----------------
extern "C" void kernel_launch(void* const* d_in, const int* in_sizes, int n_in,
                              void* d_out, int out_size) {
    const float* emb = (const float*)d_in[0];
    const int*   tt  = (const int*)  d_in[1];
    const float* am  = (const float*)d_in[2];
    const float* wq  = (const float*)d_in[3];
    const float* bq  = (const float*)d_in[4];
    const float* wk  = (const float*)d_in[5];
    const float* bk  = (const float*)d_in[6];
    const float* wv  = (const float*)d_in[7];
    const float* bv  = (const float*)d_in[8];
    const float* wo  = (const float*)d_in[9];
    const float* wg  = (const float*)d_in[10];
    const float* wu  = (const float*)d_in[11];
    const float* wd  = (const float*)d_in[12];
    const float* ln1 = (const float*)d_in[13];
    const float* ln2 = (const float*)d_in[14];
    const float* lnf = (const float*)d_in[15];

    float *x, *h, *q, *k, *v, *ao, *gt, *up;
    float *wqT, *wkT, *wvT, *woT, *wgT, *wuT, *wdT;
    cudaGetSymbolAddress((void**)&x,  g_x);
    cudaGetSymbolAddress((void**)&h,  g_h);
    cudaGetSymbolAddress((void**)&q,  g_q);
    cudaGetSymbolAddress((void**)&k,  g_k);
    cudaGetSymbolAddress((void**)&v,  g_v);
    cudaGetSymbolAddress((void**)&ao, g_ao);
    cudaGetSymbolAddress((void**)&gt, g_gate);
    cudaGetSymbolAddress((void**)&up, g_up);
    cudaGetSymbolAddress((void**)&wqT, g_wqT);
    cudaGetSymbolAddress((void**)&wkT, g_wkT);
    cudaGetSymbolAddress((void**)&wvT, g_wvT);
    cudaGetSymbolAddress((void**)&woT, g_woT);
    cudaGetSymbolAddress((void**)&wgT, g_wgT);
    cudaGetSymbolAddress((void**)&wuT, g_wuT);
    cudaGetSymbolAddress((void**)&wdT, g_wdT);

    // weight transposes (K-major B operands)
    transpose_k<<<dim3(QKD/32, DM/32, NL), 256>>>(wq, wqT, DM, QKD);
    transpose_k<<<dim3(KVD/32, DM/32, NL), 256>>>(wk, wkT, DM, KVD);
    transpose_k<<<dim3(KVD/32, DM/32, NL), 256>>>(wv, wvT, DM, KVD);
    transpose_k<<<dim3(DM/32, QKD/32, NL), 256>>>(wo, woT, QKD, DM);
    transpose_k<<<dim3(IFF/32, DM/32, NL), 256>>>(wg, wgT, DM, IFF);
    transpose_k<<<dim3(IFF/32, DM/32, NL), 256>>>(wu, wuT, DM, IFF);
    transpose_k<<<dim3(DM/32, IFF/32, NL), 256>>>(wd, wdT, IFF, DM);

    int nx = ROWS * DM;
    copy_k<<<(nx + 255) / 256, 256>>>(x, emb, nx);

    dim3 gQK (QKD / 128, ROWS / 128);   // (7, 32)
    dim3 gKV (KVD / 128, ROWS / 128);   // (1, 32)
    dim3 gFF (IFF / 128, ROWS / 128);   // (38, 32)
    dim3 gDM (DM  / 128, ROWS / 128);   // (7, 32)
    dim3 gAt (SEQ / 4, NHQ, BSZ);

    for (int l = 0; l < NL; l++) {
        rmsnorm_k<<<ROWS, 256>>>(x, ln1 + (size_t)l * DM, h);

        mgemm_k<0><<<gQK, 256>>>(h, wqT + (size_t)l * QKD * DM,
                                 bq + (size_t)l * QKD, nullptr, q, ROWS, QKD, DM);
        mgemm_k<0><<<gKV, 256>>>(h, wkT + (size_t)l * KVD * DM,
                                 bk + (size_t)l * KVD, nullptr, k, ROWS, KVD, DM);
        mgemm_k<0><<<gKV, 256>>>(h, wvT + (size_t)l * KVD * DM,
                                 bv + (size_t)l * KVD, nullptr, v, ROWS, KVD, DM);

        rope_k<<<ROWS, NHQ * 32>>>(q, NHQ);
        rope_k<<<ROWS, NHKV * 32>>>(k, NHKV);

        attn_k<<<gAt, 128>>>(q, k, v, tt, am, ao);

        mgemm_k<1><<<gDM, 256>>>(ao, woT + (size_t)l * DM * QKD,
                                 nullptr, nullptr, x, ROWS, DM, QKD);

        rmsnorm_k<<<ROWS, 256>>>(x, ln2 + (size_t)l * DM, h);

        mgemm_k<0><<<gFF, 256>>>(h, wgT + (size_t)l * IFF * DM,
                                 nullptr, nullptr, gt, ROWS, IFF, DM);
        mgemm_k<2><<<gFF, 256>>>(h, wuT + (size_t)l * IFF * DM,
                                 nullptr, gt, up, ROWS, IFF, DM);
        mgemm_k<1><<<gDM, 256>>>(up, wdT + (size_t)l * DM * IFF,
                                 nullptr, nullptr, x, ROWS, DM, IFF);
    }

    rmsnorm_k<<<ROWS, 256>>>(x, lnf, (float*)d_out);
}

// round 4
// speedup vs baseline: 3.2578x; 1.3163x over previous
#include <cuda_runtime.h>
#include <math.h>
#include <stdint.h>

// Problem constants
#define BSZ 2
#define SEQ 2048
#define DM  896
#define NL  24
#define NHQ 14
#define NHKV 2
#define DH  64
#define IFF 4864
#define ROWS (BSZ*SEQ)          // 4096
#define QKD (NHQ*DH)            // 896
#define KVD (NHKV*DH)           // 128
#define QKVD (QKD + 2*KVD)      // 1152

// ---------------- scratch (device globals; no allocations allowed) ----------
__device__ float g_x  [ROWS*DM];
__device__ float g_h  [ROWS*DM];
__device__ float g_qkv[(size_t)ROWS*QKVD];
__device__ float g_ao [ROWS*QKD];
__device__ float g_gate[(size_t)ROWS*IFF];
__device__ float g_up  [(size_t)ROWS*IFF];
// transposed (K-major) weights, pre-rounded to tf32
__device__ float g_wqkvT[(size_t)NL*QKVD*DM];
__device__ float g_woT  [(size_t)NL*DM*QKD];
__device__ float g_wgT  [(size_t)NL*IFF*DM];
__device__ float g_wuT  [(size_t)NL*IFF*DM];
__device__ float g_wdT  [(size_t)NL*DM*IFF];
__device__ float g_bqkv [NL*QKVD];

// ---------------- PTX helpers ----------------
__device__ __forceinline__ uint32_t smem_u32(const void* p) {
    uint32_t a;
    asm("{ .reg .u64 t; cvta.to.shared.u64 t, %1; cvt.u32.u64 %0, t; }" : "=r"(a) : "l"(p));
    return a;
}
__device__ __forceinline__ void cp_async16(uint32_t s, const void* g) {
    asm volatile("cp.async.cg.shared.global [%0], [%1], 16;\n" :: "r"(s), "l"(g));
}
__device__ __forceinline__ void cp_commit() { asm volatile("cp.async.commit_group;\n" ::: "memory"); }
template <int N>
__device__ __forceinline__ void cp_wait() { asm volatile("cp.async.wait_group %0;\n" :: "n"(N) : "memory"); }

__device__ __forceinline__ uint32_t f2tf(float x) {
    uint32_t r;
    asm("cvt.rna.tf32.f32 %0, %1;" : "=r"(r) : "f"(x));
    return r;
}
__device__ __forceinline__ float tfr(float x) { return __uint_as_float(f2tf(x)); }

__device__ __forceinline__ void mma8(float* c, const uint32_t* a, const uint32_t* b) {
    asm volatile(
        "mma.sync.aligned.m16n8k8.row.col.f32.tf32.tf32.f32 "
        "{%0,%1,%2,%3}, {%4,%5,%6,%7}, {%8,%9}, {%0,%1,%2,%3};"
        : "+f"(c[0]), "+f"(c[1]), "+f"(c[2]), "+f"(c[3])
        : "r"(a[0]), "r"(a[1]), "r"(a[2]), "r"(a[3]), "r"(b[0]), "r"(b[1]));
}

// ---------------- elementwise copy ----------------
__global__ void copy_k(float* __restrict__ dst, const float* __restrict__ src, int n) {
    int i = blockIdx.x * blockDim.x + threadIdx.x;
    if (i < n) dst[i] = src[i];
}

// ---------------- bias pack: [bq | bk | bv] per layer ----------------
__global__ void biaspack_k(const float* __restrict__ bq, const float* __restrict__ bk,
                           const float* __restrict__ bv, float* __restrict__ out) {
    int i = blockIdx.x * blockDim.x + threadIdx.x;
    if (i >= NL * QKVD) return;
    int l = i / QKVD, c = i % QKVD;
    float v;
    if (c < QKD) v = bq[l * QKD + c];
    else if (c < QKD + KVD) v = bk[l * KVD + c - QKD];
    else v = bv[l * KVD + c - QKD - KVD];
    out[i] = v;
}

// ---------------- transpose + tf32 round: out[z][c][r] = tf(in[z][r][c]) ----
__global__ __launch_bounds__(256) void transpose_k(const float* __restrict__ in,
                                                   float* __restrict__ out,
                                                   int R, int C,
                                                   size_t inLS, size_t outLS) {
    __shared__ float t[32][33];
    const float* ip = in + (size_t)blockIdx.z * inLS;
    float* op = out + (size_t)blockIdx.z * outLS;
    int r0 = blockIdx.y * 32, c0 = blockIdx.x * 32;
    int tx = threadIdx.x & 31, ty = threadIdx.x >> 5;
#pragma unroll
    for (int i = 0; i < 32; i += 8)
        t[ty + i][tx] = ip[(size_t)(r0 + ty + i) * C + c0 + tx];
    __syncthreads();
#pragma unroll
    for (int i = 0; i < 32; i += 8)
        op[(size_t)(c0 + ty + i) * R + r0 + tx] = tfr(t[tx][ty + i]);
}

// ---------------- RMSNorm (RND: round output to tf32) ----------------
template <bool RND>
__global__ __launch_bounds__(256) void rmsnorm_k(const float* __restrict__ x,
                                                 const float* __restrict__ w,
                                                 float* __restrict__ o) {
    int row = blockIdx.x;
    const float* xr = x + (size_t)row * DM;
    float s = 0.f;
    for (int i = threadIdx.x; i < DM; i += 256) { float v = xr[i]; s += v * v; }
    __shared__ float red[256];
    red[threadIdx.x] = s;
    __syncthreads();
    for (int st = 128; st > 0; st >>= 1) {
        if (threadIdx.x < st) red[threadIdx.x] += red[threadIdx.x + st];
        __syncthreads();
    }
    float r = rsqrtf(red[0] / (float)DM + 1e-6f);
    float* orow = o + (size_t)row * DM;
    for (int i = threadIdx.x; i < DM; i += 256) {
        float v = xr[i] * r * w[i];
        orow[i] = RND ? tfr(v) : v;
    }
}

// ---------------- mma.sync tf32 GEMM: C[M,N] = A[M,K] @ Bt[N,K]^T ------------
// Inputs A, Bt pre-rounded to tf32. CTA 128x128, BK=16, 8 warps, 3-stage.
// EPI 0: C = acc + bias ;  EPI 1: C += acc ;  EPI 2: C = tf(silu(G) * acc)
#define SPITCH 20
#define STG_F  (128 * SPITCH)            // floats per A (or B) stage
template <int EPI>
__global__ __launch_bounds__(256, 2) void mgemm_k(const float* __restrict__ A,
                                                  const float* __restrict__ Bt,
                                                  const float* __restrict__ bias,
                                                  const float* __restrict__ G,
                                                  float* __restrict__ C,
                                                  int M, int N, int K) {
    extern __shared__ float smemf[];
    uint32_t sbase = smem_u32(smemf);

    int tid = threadIdx.x;
    int wid = tid >> 5;
    int lane = tid & 31;
    int gid = lane >> 2, t4 = lane & 3;
    int wm = wid & 1, wn = wid >> 1;
    int row0 = blockIdx.y * 128, col0 = blockIdx.x * 128;

    const int NK = K >> 4;
    float acc[4][4][4] = {};

    // per-thread load coords
    int lr = tid >> 2, lc = tid & 3;                     // row, 16B-chunk
    uint32_t loff = (uint32_t)(lr * SPITCH + lc * 4) * 4;
    const float* Ag = A  + (size_t)(row0 + lr) * K + lc * 4;
    const float* Bg = Bt + (size_t)(col0 + lr) * K + lc * 4;
    const float* Ag2 = Ag + 64 * K;                      // second half rows
    const float* Bg2 = Bg + 64 * K;
    uint32_t loff2 = loff + (uint32_t)(64 * SPITCH) * 4;

#define PREFETCH(stg, k0)                                             \
    do {                                                              \
        uint32_t sa = sbase + (stg) * (2 * STG_F * 4);                \
        uint32_t sb = sa + STG_F * 4;                                 \
        cp_async16(sa + loff,  Ag  + (k0));                           \
        cp_async16(sa + loff2, Ag2 + (k0));                           \
        cp_async16(sb + loff,  Bg  + (k0));                           \
        cp_async16(sb + loff2, Bg2 + (k0));                           \
    } while (0)

    PREFETCH(0, 0); cp_commit();
    PREFETCH(1, 16); cp_commit();

    for (int kt = 0; kt < NK; kt++) {
        if (kt + 2 < NK) cp_wait<1>(); else cp_wait<0>();
        __syncthreads();
        if (kt + 2 < NK) {
            PREFETCH((kt + 2) % 3, (kt + 2) << 4);
            cp_commit();
        }
        int s = kt % 3;
        const float* as = smemf + s * (2 * STG_F);
        const float* bs = as + STG_F;
#pragma unroll
        for (int ks = 0; ks < 2; ks++) {
            uint32_t af[4][4];
            int kc = ks * 8 + t4;
#pragma unroll
            for (int mt = 0; mt < 4; mt++) {
                int row = wm * 64 + mt * 16 + gid;
                af[mt][0] = __float_as_uint(as[row * SPITCH + kc]);
                af[mt][1] = __float_as_uint(as[(row + 8) * SPITCH + kc]);
                af[mt][2] = __float_as_uint(as[row * SPITCH + kc + 4]);
                af[mt][3] = __float_as_uint(as[(row + 8) * SPITCH + kc + 4]);
            }
            uint32_t bf[4][2];
#pragma unroll
            for (int nt = 0; nt < 4; nt++) {
                int col = wn * 32 + nt * 8 + gid;
                bf[nt][0] = __float_as_uint(bs[col * SPITCH + kc]);
                bf[nt][1] = __float_as_uint(bs[col * SPITCH + kc + 4]);
            }
#pragma unroll
            for (int mt = 0; mt < 4; mt++)
#pragma unroll
                for (int nt = 0; nt < 4; nt++)
                    mma8(acc[mt][nt], af[mt], bf[nt]);
        }
    }
#undef PREFETCH

    // epilogue
#pragma unroll
    for (int mt = 0; mt < 4; mt++) {
#pragma unroll
        for (int nt = 0; nt < 4; nt++) {
            int rg = row0 + wm * 64 + mt * 16 + gid;
            int cg = col0 + wn * 32 + nt * 8 + 2 * t4;
#pragma unroll
            for (int half = 0; half < 2; half++) {
                int r = rg + half * 8;
                float v0 = acc[mt][nt][half * 2 + 0];
                float v1 = acc[mt][nt][half * 2 + 1];
                size_t idx = (size_t)r * N + cg;
                if (EPI == 0) {
                    float b0 = bias ? bias[cg] : 0.f;
                    float b1 = bias ? bias[cg + 1] : 0.f;
                    *(float2*)(C + idx) = make_float2(v0 + b0, v1 + b1);
                } else if (EPI == 1) {
                    float2 o = *(float2*)(C + idx);
                    o.x += v0; o.y += v1;
                    *(float2*)(C + idx) = o;
                } else {
                    float g0 = G[idx], g1 = G[idx + 1];
                    *(float2*)(C + idx) = make_float2(
                        tfr(v0 * (g0 / (1.f + expf(-g0)))),
                        tfr(v1 * (g1 / (1.f + expf(-g1)))));
                }
            }
        }
    }
}

// ---------------- RoPE on packed qkv (q heads 0-13, k heads 14-15) ----------
__global__ void rope_k(float* __restrict__ p) {
    int row = blockIdx.x;
    int s = row & (SEQ - 1);
    int t = threadIdx.x;
    int h = t >> 5, i = t & 31;          // h in 0..15; cols h*64 are contiguous q|k
    float inv = 1.0f / powf(1.0e6f, (float)i / 32.0f);
    float ang = (float)s * inv;
    float c = cosf(ang), sn = sinf(ang);
    float* base = p + (size_t)row * QKVD + h * 64;
    float x1 = base[i], x2 = base[i + 32];
    base[i]      = x1 * c - x2 * sn;
    base[i + 32] = x2 * c + x1 * sn;
}

// ---------------- Attention: 64 queries/block, 16 per warp ------------------
// grid (SEQ/64, NHQ, BSZ), 128 threads. Dynamic smem.
#define ATTN_SMEM 51200
__global__ __launch_bounds__(128) void attn_k(const float* __restrict__ qkv,
                                              const int* __restrict__ tt,
                                              const float* __restrict__ am,
                                              float* __restrict__ out) {
    extern __shared__ float sm[];
    float* Ks  = sm;             // [64][65]
    float* Vs  = sm + 4160;      // [64][65]
    float* qs  = sm + 8320;      // [64][64]
    float* ps  = sm + 12416;     // [4][64]
    float* msf = sm + 12672;     // [64]
    int*   tts = (int*)(sm + 12736);

    int b = blockIdx.z, h = blockIdx.y;
    int w = threadIdx.x >> 5;
    int lane = threadIdx.x & 31;
    int tid = threadIdx.x;
    int qt0 = blockIdx.x * 64;
    int kvh = h / (NHQ / NHKV);
    int j1 = lane, j2 = lane + 32;

    // load q tile: 64 rows x 64 dims (float4)
    for (int idx = tid; idx < 64 * 16; idx += 128) {
        int r = idx >> 4, c4 = (idx & 15) * 4;
        float4 qv = *(const float4*)(qkv + (size_t)(b * SEQ + qt0 + r) * QKVD + h * 64 + c4);
        *(float4*)(qs + r * 64 + c4) = qv;   // 64*4=256B rows, 16B aligned
    }

    int tqv[16];
#pragma unroll
    for (int qq = 0; qq < 16; qq++)
        tqv[qq] = tt[b * SEQ + qt0 + w * 16 + qq];

    float m[16], l[16], o0[16], o1[16];
#pragma unroll
    for (int qq = 0; qq < 16; qq++) { m[qq] = -INFINITY; l[qq] = 0.f; o0[qq] = 0.f; o1[qq] = 0.f; }

    const float scale = 0.125f;
    const float NEG = -3.0e38f;

    for (int kt = 0; kt < SEQ; kt += 64) {
        __syncthreads();
        for (int idx = tid; idx < 64 * 16; idx += 128) {
            int r = idx >> 4, c4 = (idx & 15) * 4;
            const float* base = qkv + (size_t)(b * SEQ + kt + r) * QKVD;
            float4 kv = *(const float4*)(base + QKD + kvh * 64 + c4);
            float4 vv = *(const float4*)(base + QKD + KVD + kvh * 64 + c4);
            Ks[r * 65 + c4] = kv.x; Ks[r * 65 + c4 + 1] = kv.y;
            Ks[r * 65 + c4 + 2] = kv.z; Ks[r * 65 + c4 + 3] = kv.w;
            Vs[r * 65 + c4] = vv.x; Vs[r * 65 + c4 + 1] = vv.y;
            Vs[r * 65 + c4 + 2] = vv.z; Vs[r * 65 + c4 + 3] = vv.w;
        }
        if (tid < 64) {
            tts[tid] = tt[b * SEQ + kt + tid];
            msf[tid] = am[b * SEQ + kt + tid];
        }
        __syncthreads();

        int tk1 = tts[j1], tk2 = tts[j2];
        float pad1 = (1.f - msf[j1]) * NEG, pad2 = (1.f - msf[j2]) * NEG;
        int ki1 = kt + j1, ki2 = kt + j2;

#pragma unroll
        for (int qq = 0; qq < 16; qq++) {
            int qi = qt0 + w * 16 + qq;
            int tq = tqv[qq];
            const float* qrow = qs + (w * 16 + qq) * 64;
            float s1 = 0.f, s2 = 0.f;
#pragma unroll 8
            for (int d = 0; d < DH; d++) {
                float qd = qrow[d];
                s1 += qd * Ks[j1 * 65 + d];
                s2 += qd * Ks[j2 * 65 + d];
            }
            bool al1 = (tq == 0) ? (tk1 == 0) : ((tk1 == 0) || (ki1 <= qi));
            bool al2 = (tq == 0) ? (tk2 == 0) : ((tk2 == 0) || (ki2 <= qi));
            s1 = fmaxf(s1 * scale + (al1 ? 0.f : NEG) + pad1, -3.3e38f);
            s2 = fmaxf(s2 * scale + (al2 ? 0.f : NEG) + pad2, -3.3e38f);

            float tm = fmaxf(s1, s2);
#pragma unroll
            for (int o = 16; o; o >>= 1) tm = fmaxf(tm, __shfl_xor_sync(0xffffffffu, tm, o));
            float mn = fmaxf(m[qq], tm);
            float corr = expf(m[qq] - mn);
            float p1 = expf(s1 - mn), p2 = expf(s2 - mn);
            ps[w * 64 + j1] = p1; ps[w * 64 + j2] = p2;
            float psum = p1 + p2;
#pragma unroll
            for (int o = 16; o; o >>= 1) psum += __shfl_xor_sync(0xffffffffu, psum, o);
            l[qq] = l[qq] * corr + psum;
            o0[qq] *= corr; o1[qq] *= corr;
            m[qq] = mn;
            __syncwarp();
#pragma unroll 8
            for (int j = 0; j < 64; j++) {
                float pj = ps[w * 64 + j];
                o0[qq] += pj * Vs[j * 65 + j1];
                o1[qq] += pj * Vs[j * 65 + j2];
            }
            __syncwarp();
        }
    }

#pragma unroll
    for (int qq = 0; qq < 16; qq++) {
        float invl = 1.0f / l[qq];
        float* orow = out + (size_t)(b * SEQ + qt0 + w * 16 + qq) * QKD + h * 64;
        orow[j1] = tfr(o0[qq] * invl);
        orow[j2] = tfr(o1[qq] * invl);
    }
}

// ---------------- host driver ----------------
extern "C" void kernel_launch(void* const* d_in, const int* in_sizes, int n_in,
                              void* d_out, int out_size) {
    const float* emb = (const float*)d_in[0];
    const int*   tt  = (const int*)  d_in[1];
    const float* am  = (const float*)d_in[2];
    const float* wq  = (const float*)d_in[3];
    const float* bq  = (const float*)d_in[4];
    const float* wk  = (const float*)d_in[5];
    const float* bk  = (const float*)d_in[6];
    const float* wv  = (const float*)d_in[7];
    const float* bv  = (const float*)d_in[8];
    const float* wo  = (const float*)d_in[9];
    const float* wg  = (const float*)d_in[10];
    const float* wu  = (const float*)d_in[11];
    const float* wd  = (const float*)d_in[12];
    const float* ln1 = (const float*)d_in[13];
    const float* ln2 = (const float*)d_in[14];
    const float* lnf = (const float*)d_in[15];

    float *x, *h, *qkv, *ao, *gt, *up;
    float *wqkvT, *woT, *wgT, *wuT, *wdT, *bqkv;
    cudaGetSymbolAddress((void**)&x,   g_x);
    cudaGetSymbolAddress((void**)&h,   g_h);
    cudaGetSymbolAddress((void**)&qkv, g_qkv);
    cudaGetSymbolAddress((void**)&ao,  g_ao);
    cudaGetSymbolAddress((void**)&gt,  g_gate);
    cudaGetSymbolAddress((void**)&up,  g_up);
    cudaGetSymbolAddress((void**)&wqkvT, g_wqkvT);
    cudaGetSymbolAddress((void**)&woT, g_woT);
    cudaGetSymbolAddress((void**)&wgT, g_wgT);
    cudaGetSymbolAddress((void**)&wuT, g_wuT);
    cudaGetSymbolAddress((void**)&wdT, g_wdT);
    cudaGetSymbolAddress((void**)&bqkv, g_bqkv);

    const int GSMEM = 3 * 2 * STG_F * 4;   // 61440 bytes
    cudaFuncSetAttribute(mgemm_k<0>, cudaFuncAttributeMaxDynamicSharedMemorySize, GSMEM);
    cudaFuncSetAttribute(mgemm_k<1>, cudaFuncAttributeMaxDynamicSharedMemorySize, GSMEM);
    cudaFuncSetAttribute(mgemm_k<2>, cudaFuncAttributeMaxDynamicSharedMemorySize, GSMEM);
    cudaFuncSetAttribute(attn_k, cudaFuncAttributeMaxDynamicSharedMemorySize, ATTN_SMEM);

    // weight transposes (+tf32 rounding); qkv packed into [q|k|v] rows
    size_t oLS = (size_t)QKVD * DM;
    transpose_k<<<dim3(QKD/32, DM/32, NL), 256>>>(wq, wqkvT,            DM, QKD, (size_t)DM*QKD, oLS);
    transpose_k<<<dim3(KVD/32, DM/32, NL), 256>>>(wk, wqkvT + (size_t)QKD*DM,       DM, KVD, (size_t)DM*KVD, oLS);
    transpose_k<<<dim3(KVD/32, DM/32, NL), 256>>>(wv, wqkvT + (size_t)(QKD+KVD)*DM, DM, KVD, (size_t)DM*KVD, oLS);
    transpose_k<<<dim3(DM/32, QKD/32, NL), 256>>>(wo, woT, QKD, DM, (size_t)QKD*DM, (size_t)DM*QKD);
    transpose_k<<<dim3(IFF/32, DM/32, NL), 256>>>(wg, wgT, DM, IFF, (size_t)DM*IFF, (size_t)IFF*DM);
    transpose_k<<<dim3(IFF/32, DM/32, NL), 256>>>(wu, wuT, DM, IFF, (size_t)DM*IFF, (size_t)IFF*DM);
    transpose_k<<<dim3(DM/32, IFF/32, NL), 256>>>(wd, wdT, IFF, DM, (size_t)IFF*DM, (size_t)DM*IFF);
    biaspack_k<<<(NL*QKVD + 255)/256, 256>>>(bq, bk, bv, bqkv);

    int nx = ROWS * DM;
    copy_k<<<(nx + 255) / 256, 256>>>(x, emb, nx);

    dim3 gQKV(QKVD / 128, ROWS / 128);   // (9, 32)
    dim3 gDM (DM   / 128, ROWS / 128);   // (7, 32)
    dim3 gFF (IFF  / 128, ROWS / 128);   // (38, 32)
    dim3 gAt (SEQ / 64, NHQ, BSZ);       // (32, 14, 2)

    for (int l = 0; l < NL; l++) {
        rmsnorm_k<true><<<ROWS, 256>>>(x, ln1 + (size_t)l * DM, h);

        mgemm_k<0><<<gQKV, 256, GSMEM>>>(h, wqkvT + (size_t)l * QKVD * DM,
                                         bqkv + (size_t)l * QKVD, nullptr, qkv,
                                         ROWS, QKVD, DM);

        rope_k<<<ROWS, 16 * 32>>>(qkv);

        attn_k<<<gAt, 128, ATTN_SMEM>>>(qkv, tt, am, ao);

        mgemm_k<1><<<gDM, 256, GSMEM>>>(ao, woT + (size_t)l * DM * QKD,
                                        nullptr, nullptr, x, ROWS, DM, QKD);

        rmsnorm_k<true><<<ROWS, 256>>>(x, ln2 + (size_t)l * DM, h);

        mgemm_k<0><<<gFF, 256, GSMEM>>>(h, wgT + (size_t)l * IFF * DM,
                                        nullptr, nullptr, gt, ROWS, IFF, DM);
        mgemm_k<2><<<gFF, 256, GSMEM>>>(h, wuT + (size_t)l * IFF * DM,
                                        nullptr, gt, up, ROWS, IFF, DM);
        mgemm_k<1><<<gDM, 256, GSMEM>>>(up, wdT + (size_t)l * DM * IFF,
                                        nullptr, nullptr, x, ROWS, DM, IFF);
    }

    rmsnorm_k<false><<<ROWS, 256>>>(x, lnf, (float*)d_out);
}

// round 8
// speedup vs baseline: 3.6725x; 1.1273x over previous
#include <cuda_runtime.h>
#include <cuda_fp16.h>
#include <math.h>
#include <stdint.h>

// Problem constants
#define BSZ 2
#define SEQ 2048
#define DM  896
#define NL  24
#define NHQ 14
#define NHKV 2
#define DH  64
#define IFF 4864
#define ROWS (BSZ*SEQ)          // 4096
#define QKD (NHQ*DH)            // 896
#define KVD (NHKV*DH)           // 128
#define QKVD (QKD + 2*KVD)      // 1152

// ---------------- scratch (device globals; no allocations allowed) ----------
__device__ float  g_x  [ROWS*DM];
__device__ __half g_h  [ROWS*DM];
__device__ float  g_qkv[(size_t)ROWS*QKVD];
__device__ __half g_ao [ROWS*QKD];
__device__ float  g_gate[(size_t)ROWS*IFF];
__device__ __half g_up  [(size_t)ROWS*IFF];
// transposed (K-major) weights in fp16
__device__ __half g_wqkvT[(size_t)NL*QKVD*DM];
__device__ __half g_woT  [(size_t)NL*DM*QKD];
__device__ __half g_wgT  [(size_t)NL*IFF*DM];
__device__ __half g_wuT  [(size_t)NL*IFF*DM];
__device__ __half g_wdT  [(size_t)NL*DM*IFF];
__device__ float  g_bqkv [NL*QKVD];

// ---------------- PTX helpers ----------------
__device__ __forceinline__ uint32_t smem_u32(const void* p) {
    uint32_t a;
    asm("{ .reg .u64 t; cvta.to.shared.u64 t, %1; cvt.u32.u64 %0, t; }" : "=r"(a) : "l"(p));
    return a;
}
__device__ __forceinline__ void cp_async16(uint32_t s, const void* g) {
    asm volatile("cp.async.cg.shared.global [%0], [%1], 16;\n" :: "r"(s), "l"(g));
}
__device__ __forceinline__ void cp_commit() { asm volatile("cp.async.commit_group;\n" ::: "memory"); }
template <int N>
__device__ __forceinline__ void cp_wait() { asm volatile("cp.async.wait_group %0;\n" :: "n"(N) : "memory"); }

__device__ __forceinline__ void mma16(float* c, const uint32_t* a, const uint32_t* b) {
    asm volatile(
        "mma.sync.aligned.m16n8k16.row.col.f32.f16.f16.f32 "
        "{%0,%1,%2,%3}, {%4,%5,%6,%7}, {%8,%9}, {%0,%1,%2,%3};"
        : "+f"(c[0]), "+f"(c[1]), "+f"(c[2]), "+f"(c[3])
        : "r"(a[0]), "r"(a[1]), "r"(a[2]), "r"(a[3]), "r"(b[0]), "r"(b[1]));
}

// ---------------- elementwise copy ----------------
__global__ void copy_k(float* __restrict__ dst, const float* __restrict__ src, int n) {
    int i = blockIdx.x * blockDim.x + threadIdx.x;
    if (i < n) dst[i] = src[i];
}

// ---------------- bias pack: [bq | bk | bv] per layer ----------------
__global__ void biaspack_k(const float* __restrict__ bq, const float* __restrict__ bk,
                           const float* __restrict__ bv, float* __restrict__ out) {
    int i = blockIdx.x * blockDim.x + threadIdx.x;
    if (i >= NL * QKVD) return;
    int l = i / QKVD, c = i % QKVD;
    float v;
    if (c < QKD) v = bq[l * QKD + c];
    else if (c < QKD + KVD) v = bk[l * KVD + c - QKD];
    else v = bv[l * KVD + c - QKD - KVD];
    out[i] = v;
}

// ---------------- transpose + fp16 round: out[z][c][r] = h(in[z][r][c]) ----
__global__ __launch_bounds__(256) void transpose_k(const float* __restrict__ in,
                                                   __half* __restrict__ out,
                                                   int R, int C,
                                                   size_t inLS, size_t outLS) {
    __shared__ float t[32][33];
    const float* ip = in + (size_t)blockIdx.z * inLS;
    __half* op = out + (size_t)blockIdx.z * outLS;
    int r0 = blockIdx.y * 32, c0 = blockIdx.x * 32;
    int tx = threadIdx.x & 31, ty = threadIdx.x >> 5;
#pragma unroll
    for (int i = 0; i < 32; i += 8)
        t[ty + i][tx] = ip[(size_t)(r0 + ty + i) * C + c0 + tx];
    __syncthreads();
#pragma unroll
    for (int i = 0; i < 32; i += 8)
        op[(size_t)(c0 + ty + i) * R + r0 + tx] = __float2half_rn(t[tx][ty + i]);
}

// ---------------- RMSNorm (templated output type) ----------------
template <typename OT>
__global__ __launch_bounds__(256) void rmsnorm_k(const float* __restrict__ x,
                                                 const float* __restrict__ w,
                                                 OT* __restrict__ o) {
    int row = blockIdx.x;
    const float* xr = x + (size_t)row * DM;
    float s = 0.f;
    for (int i = threadIdx.x; i < DM; i += 256) { float v = xr[i]; s += v * v; }
    __shared__ float red[256];
    red[threadIdx.x] = s;
    __syncthreads();
    for (int st = 128; st > 0; st >>= 1) {
        if (threadIdx.x < st) red[threadIdx.x] += red[threadIdx.x + st];
        __syncthreads();
    }
    float r = rsqrtf(red[0] / (float)DM + 1e-6f);
    OT* orow = o + (size_t)row * DM;
    for (int i = threadIdx.x; i < DM; i += 256) {
        float v = xr[i] * r * w[i];
        orow[i] = (OT)v;
    }
}

// ---------------- fp16 mma GEMM: C[M,N] = A[M,K] @ Bt[N,K]^T ----------------
// A, Bt fp16; accumulate fp32. CTA 128x128, BK=32, 8 warps (2x4), 3-stage.
// EPI 0: C(f32) = acc + bias ;  EPI 1: C(f32) += acc ;
// EPI 2: C(f16) = h(silu(G) * acc)
#define PH 40                     // halves per smem row
#define STG_H (128 * PH)          // halves per A (or B) stage
template <int EPI, typename CT>
__global__ __launch_bounds__(256, 2) void mgemm_k(const __half* __restrict__ A,
                                                  const __half* __restrict__ Bt,
                                                  const float* __restrict__ bias,
                                                  const float* __restrict__ G,
                                                  CT* __restrict__ C,
                                                  int M, int N, int K) {
    extern __shared__ __half smemh[];
    uint32_t sbase = smem_u32(smemh);

    int tid = threadIdx.x;
    int wid = tid >> 5;
    int lane = tid & 31;
    int gid = lane >> 2, t4 = lane & 3;
    int wm = wid & 1, wn = wid >> 1;
    int row0 = blockIdx.y * 128, col0 = blockIdx.x * 128;

    const int NK = K >> 5;
    float acc[4][4][4] = {};

    // per-thread load coords: 8 halves (16B) per cp; 4 chunks/row of 32 halves
    int lr = tid >> 2, lc = tid & 3;
    uint32_t loff = (uint32_t)(lr * PH + lc * 8) * 2;
    const __half* Ag  = A  + (size_t)(row0 + lr) * K + lc * 8;
    const __half* Bg  = Bt + (size_t)(col0 + lr) * K + lc * 8;
    const __half* Ag2 = Ag + 64 * K;
    const __half* Bg2 = Bg + 64 * K;
    uint32_t loff2 = loff + (uint32_t)(64 * PH) * 2;

#define PREFETCH(stg, k0)                                             \
    do {                                                              \
        uint32_t sa = sbase + (stg) * (2 * STG_H * 2);                \
        uint32_t sb = sa + STG_H * 2;                                 \
        cp_async16(sa + loff,  Ag  + (k0));                           \
        cp_async16(sa + loff2, Ag2 + (k0));                           \
        cp_async16(sb + loff,  Bg  + (k0));                           \
        cp_async16(sb + loff2, Bg2 + (k0));                           \
    } while (0)

    PREFETCH(0, 0); cp_commit();
    PREFETCH(1, 32); cp_commit();

    for (int kt = 0; kt < NK; kt++) {
        if (kt + 2 < NK) cp_wait<1>(); else cp_wait<0>();
        __syncthreads();
        if (kt + 2 < NK) {
            PREFETCH((kt + 2) % 3, (kt + 2) << 5);
            cp_commit();
        }
        int s = kt % 3;
        const __half* as = smemh + s * (2 * STG_H);
        const __half* bs = as + STG_H;
#pragma unroll
        for (int ks = 0; ks < 2; ks++) {
            int kc = ks * 16 + 2 * t4;
            uint32_t af[4][4];
#pragma unroll
            for (int mt = 0; mt < 4; mt++) {
                int row = wm * 64 + mt * 16 + gid;
                af[mt][0] = *(const uint32_t*)(as + row * PH + kc);
                af[mt][1] = *(const uint32_t*)(as + (row + 8) * PH + kc);
                af[mt][2] = *(const uint32_t*)(as + row * PH + kc + 8);
                af[mt][3] = *(const uint32_t*)(as + (row + 8) * PH + kc + 8);
            }
            uint32_t bf[4][2];
#pragma unroll
            for (int nt = 0; nt < 4; nt++) {
                int col = wn * 32 + nt * 8 + gid;
                bf[nt][0] = *(const uint32_t*)(bs + col * PH + kc);
                bf[nt][1] = *(const uint32_t*)(bs + col * PH + kc + 8);
            }
#pragma unroll
            for (int mt = 0; mt < 4; mt++)
#pragma unroll
                for (int nt = 0; nt < 4; nt++)
                    mma16(acc[mt][nt], af[mt], bf[nt]);
        }
    }
#undef PREFETCH

    // epilogue
#pragma unroll
    for (int mt = 0; mt < 4; mt++) {
#pragma unroll
        for (int nt = 0; nt < 4; nt++) {
            int rg = row0 + wm * 64 + mt * 16 + gid;
            int cg = col0 + wn * 32 + nt * 8 + 2 * t4;
#pragma unroll
            for (int half = 0; half < 2; half++) {
                int r = rg + half * 8;
                float v0 = acc[mt][nt][half * 2 + 0];
                float v1 = acc[mt][nt][half * 2 + 1];
                size_t idx = (size_t)r * N + cg;
                if (EPI == 0) {
                    float b0 = bias ? bias[cg] : 0.f;
                    float b1 = bias ? bias[cg + 1] : 0.f;
                    *(float2*)((float*)C + idx) = make_float2(v0 + b0, v1 + b1);
                } else if (EPI == 1) {
                    float2 o = *(float2*)((float*)C + idx);
                    o.x += v0; o.y += v1;
                    *(float2*)((float*)C + idx) = o;
                } else {
                    float g0 = G[idx], g1 = G[idx + 1];
                    __half2 hv = __floats2half2_rn(v0 * (g0 / (1.f + expf(-g0))),
                                                   v1 * (g1 / (1.f + expf(-g1))));
                    *(__half2*)((__half*)C + idx) = hv;
                }
            }
        }
    }
}

// ---------------- RoPE on packed qkv (q heads 0-13, k heads 14-15) ----------
__global__ void rope_k(float* __restrict__ p) {
    int row = blockIdx.x;
    int s = row & (SEQ - 1);
    int t = threadIdx.x;
    int h = t >> 5, i = t & 31;
    float inv = 1.0f / powf(1.0e6f, (float)i / 32.0f);
    float ang = (float)s * inv;
    float c = cosf(ang), sn = sinf(ang);
    float* base = p + (size_t)row * QKVD + h * 64;
    float x1 = base[i], x2 = base[i + 32];
    base[i]      = x1 * c - x2 * sn;
    base[i + 32] = x2 * c + x1 * sn;
}

// ---------------- Attention: 64 q/block, 16/warp, float4 smem ---------------
// grid (SEQ/64, NHQ, BSZ), 128 threads.
#define PK 68
#define ATTN_SMEM 52736
__global__ __launch_bounds__(128) void attn_k(const float* __restrict__ qkv,
                                              const int* __restrict__ tt,
                                              const float* __restrict__ am,
                                              __half* __restrict__ out) {
    extern __shared__ float sm[];
    float* Ks  = sm;             // [64][PK], key-major
    float* VsT = sm + 64 * PK;   // [64][PK], d-major (transposed)
    float* qs  = sm + 2 * 64 * PK;          // [64][64]
    float* ps  = sm + 2 * 64 * PK + 4096;   // [4][64]
    float* msf = ps + 256;                  // [64]
    int*   tts = (int*)(msf + 64);

    int b = blockIdx.z, h = blockIdx.y;
    int w = threadIdx.x >> 5;
    int lane = threadIdx.x & 31;
    int tid = threadIdx.x;
    int qt0 = blockIdx.x * 64;
    int kvh = h / (NHQ / NHKV);
    int j1 = lane, j2 = lane + 32;

    // load q tile: 64 rows x 64 dims
    for (int idx = tid; idx < 64 * 16; idx += 128) {
        int r = idx >> 4, c4 = (idx & 15) * 4;
        float4 qv = *(const float4*)(qkv + (size_t)(b * SEQ + qt0 + r) * QKVD + h * 64 + c4);
        *(float4*)(qs + r * 64 + c4) = qv;
    }

    int tqv[16];
#pragma unroll
    for (int qq = 0; qq < 16; qq++)
        tqv[qq] = tt[b * SEQ + qt0 + w * 16 + qq];

    float m[16], l[16], o0[16], o1[16];
#pragma unroll
    for (int qq = 0; qq < 16; qq++) { m[qq] = -INFINITY; l[qq] = 0.f; o0[qq] = 0.f; o1[qq] = 0.f; }

    const float scale = 0.125f;
    const float NEG = -3.0e38f;

    for (int kt = 0; kt < SEQ; kt += 64) {
        __syncthreads();
        for (int idx = tid; idx < 64 * 16; idx += 128) {
            int r = idx >> 4, c4 = (idx & 15) * 4;
            const float* base = qkv + (size_t)(b * SEQ + kt + r) * QKVD;
            float4 kv = *(const float4*)(base + QKD + kvh * 64 + c4);
            float4 vv = *(const float4*)(base + QKD + KVD + kvh * 64 + c4);
            *(float4*)(Ks + r * PK + c4) = kv;
            VsT[(c4 + 0) * PK + r] = vv.x;
            VsT[(c4 + 1) * PK + r] = vv.y;
            VsT[(c4 + 2) * PK + r] = vv.z;
            VsT[(c4 + 3) * PK + r] = vv.w;
        }
        if (tid < 64) {
            tts[tid] = tt[b * SEQ + kt + tid];
            msf[tid] = am[b * SEQ + kt + tid];
        }
        __syncthreads();

        int tk1 = tts[j1], tk2 = tts[j2];
        float pad1 = (1.f - msf[j1]) * NEG, pad2 = (1.f - msf[j2]) * NEG;
        int ki1 = kt + j1, ki2 = kt + j2;

        const float4* k1p = (const float4*)(Ks + j1 * PK);
        const float4* k2p = (const float4*)(Ks + j2 * PK);
        const float4* v1p = (const float4*)(VsT + j1 * PK);
        const float4* v2p = (const float4*)(VsT + j2 * PK);
        const float4* pp  = (const float4*)(ps + w * 64);

#pragma unroll
        for (int qq = 0; qq < 16; qq++) {
            int qi = qt0 + w * 16 + qq;
            int tq = tqv[qq];
            const float4* q4p = (const float4*)(qs + (w * 16 + qq) * 64);
            float s1a = 0.f, s1b = 0.f, s2a = 0.f, s2b = 0.f;
#pragma unroll
            for (int d4 = 0; d4 < 16; d4++) {
                float4 qv = q4p[d4];
                float4 k1 = k1p[d4];
                float4 k2 = k2p[d4];
                s1a += qv.x * k1.x + qv.y * k1.y;
                s1b += qv.z * k1.z + qv.w * k1.w;
                s2a += qv.x * k2.x + qv.y * k2.y;
                s2b += qv.z * k2.z + qv.w * k2.w;
            }
            float s1 = s1a + s1b, s2 = s2a + s2b;
            bool al1 = (tq == 0) ? (tk1 == 0) : ((tk1 == 0) || (ki1 <= qi));
            bool al2 = (tq == 0) ? (tk2 == 0) : ((tk2 == 0) || (ki2 <= qi));
            s1 = fmaxf(s1 * scale + (al1 ? 0.f : NEG) + pad1, -3.3e38f);
            s2 = fmaxf(s2 * scale + (al2 ? 0.f : NEG) + pad2, -3.3e38f);

            float tm = fmaxf(s1, s2);
#pragma unroll
            for (int o = 16; o; o >>= 1) tm = fmaxf(tm, __shfl_xor_sync(0xffffffffu, tm, o));
            float mn = fmaxf(m[qq], tm);
            float corr = expf(m[qq] - mn);
            float p1 = expf(s1 - mn), p2 = expf(s2 - mn);
            ps[w * 64 + j1] = p1; ps[w * 64 + j2] = p2;
            float psum = p1 + p2;
#pragma unroll
            for (int o = 16; o; o >>= 1) psum += __shfl_xor_sync(0xffffffffu, psum, o);
            l[qq] = l[qq] * corr + psum;
            float a0 = 0.f, a1 = 0.f, b0 = 0.f, b1 = 0.f;
            __syncwarp();
#pragma unroll
            for (int j4 = 0; j4 < 16; j4++) {
                float4 pv = pp[j4];
                float4 va = v1p[j4];
                float4 vb = v2p[j4];
                a0 += pv.x * va.x + pv.y * va.y;
                a1 += pv.z * va.z + pv.w * va.w;
                b0 += pv.x * vb.x + pv.y * vb.y;
                b1 += pv.z * vb.z + pv.w * vb.w;
            }
            o0[qq] = o0[qq] * corr + a0 + a1;
            o1[qq] = o1[qq] * corr + b0 + b1;
            m[qq] = mn;
            __syncwarp();
        }
    }

#pragma unroll
    for (int qq = 0; qq < 16; qq++) {
        float invl = 1.0f / l[qq];
        __half* orow = out + (size_t)(b * SEQ + qt0 + w * 16 + qq) * QKD + h * 64;
        orow[j1] = __float2half_rn(o0[qq] * invl);
        orow[j2] = __float2half_rn(o1[qq] * invl);
    }
}

// ---------------- host driver ----------------
extern "C" void kernel_launch(void* const* d_in, const int* in_sizes, int n_in,
                              void* d_out, int out_size) {
    const float* emb = (const float*)d_in[0];
    const int*   tt  = (const int*)  d_in[1];
    const float* am  = (const float*)d_in[2];
    const float* wq  = (const float*)d_in[3];
    const float* bq  = (const float*)d_in[4];
    const float* wk  = (const float*)d_in[5];
    const float* bk  = (const float*)d_in[6];
    const float* wv  = (const float*)d_in[7];
    const float* bv  = (const float*)d_in[8];
    const float* wo  = (const float*)d_in[9];
    const float* wg  = (const float*)d_in[10];
    const float* wu  = (const float*)d_in[11];
    const float* wd  = (const float*)d_in[12];
    const float* ln1 = (const float*)d_in[13];
    const float* ln2 = (const float*)d_in[14];
    const float* lnf = (const float*)d_in[15];

    float *x, *qkv, *gt, *bqkv;
    __half *h, *ao, *up, *wqkvT, *woT, *wgT, *wuT, *wdT;
    cudaGetSymbolAddress((void**)&x,   g_x);
    cudaGetSymbolAddress((void**)&h,   g_h);
    cudaGetSymbolAddress((void**)&qkv, g_qkv);
    cudaGetSymbolAddress((void**)&ao,  g_ao);
    cudaGetSymbolAddress((void**)&gt,  g_gate);
    cudaGetSymbolAddress((void**)&up,  g_up);
    cudaGetSymbolAddress((void**)&wqkvT, g_wqkvT);
    cudaGetSymbolAddress((void**)&woT, g_woT);
    cudaGetSymbolAddress((void**)&wgT, g_wgT);
    cudaGetSymbolAddress((void**)&wuT, g_wuT);
    cudaGetSymbolAddress((void**)&wdT, g_wdT);
    cudaGetSymbolAddress((void**)&bqkv, g_bqkv);

    const int GSMEM = 3 * 2 * STG_H * 2;   // 61440 bytes
    cudaFuncSetAttribute(mgemm_k<0, float>,  cudaFuncAttributeMaxDynamicSharedMemorySize, GSMEM);
    cudaFuncSetAttribute(mgemm_k<1, float>,  cudaFuncAttributeMaxDynamicSharedMemorySize, GSMEM);
    cudaFuncSetAttribute(mgemm_k<2, __half>, cudaFuncAttributeMaxDynamicSharedMemorySize, GSMEM);
    cudaFuncSetAttribute(attn_k, cudaFuncAttributeMaxDynamicSharedMemorySize, ATTN_SMEM);

    // weight transposes (+fp16 rounding); qkv packed into [q|k|v] rows
    size_t oLS = (size_t)QKVD * DM;
    transpose_k<<<dim3(QKD/32, DM/32, NL), 256>>>(wq, wqkvT,            DM, QKD, (size_t)DM*QKD, oLS);
    transpose_k<<<dim3(KVD/32, DM/32, NL), 256>>>(wk, wqkvT + (size_t)QKD*DM,       DM, KVD, (size_t)DM*KVD, oLS);
    transpose_k<<<dim3(KVD/32, DM/32, NL), 256>>>(wv, wqkvT + (size_t)(QKD+KVD)*DM, DM, KVD, (size_t)DM*KVD, oLS);
    transpose_k<<<dim3(DM/32, QKD/32, NL), 256>>>(wo, woT, QKD, DM, (size_t)QKD*DM, (size_t)DM*QKD);
    transpose_k<<<dim3(IFF/32, DM/32, NL), 256>>>(wg, wgT, DM, IFF, (size_t)DM*IFF, (size_t)IFF*DM);
    transpose_k<<<dim3(IFF/32, DM/32, NL), 256>>>(wu, wuT, DM, IFF, (size_t)DM*IFF, (size_t)IFF*DM);
    transpose_k<<<dim3(DM/32, IFF/32, NL), 256>>>(wd, wdT, IFF, DM, (size_t)IFF*DM, (size_t)DM*IFF);
    biaspack_k<<<(NL*QKVD + 255)/256, 256>>>(bq, bk, bv, bqkv);

    int nx = ROWS * DM;
    copy_k<<<(nx + 255) / 256, 256>>>(x, emb, nx);

    dim3 gQKV(QKVD / 128, ROWS / 128);   // (9, 32)
    dim3 gDM (DM   / 128, ROWS / 128);   // (7, 32)
    dim3 gFF (IFF  / 128, ROWS / 128);   // (38, 32)
    dim3 gAt (SEQ / 64, NHQ, BSZ);       // (32, 14, 2)

    for (int l = 0; l < NL; l++) {
        rmsnorm_k<__half><<<ROWS, 256>>>(x, ln1 + (size_t)l * DM, h);

        mgemm_k<0, float><<<gQKV, 256, GSMEM>>>(h, wqkvT + (size_t)l * QKVD * DM,
                                                bqkv + (size_t)l * QKVD, nullptr, qkv,
                                                ROWS, QKVD, DM);

        rope_k<<<ROWS, 16 * 32>>>(qkv);

        attn_k<<<gAt, 128, ATTN_SMEM>>>(qkv, tt, am, ao);

        mgemm_k<1, float><<<gDM, 256, GSMEM>>>(ao, woT + (size_t)l * DM * QKD,
                                               nullptr, nullptr, x, ROWS, DM, QKD);

        rmsnorm_k<__half><<<ROWS, 256>>>(x, ln2 + (size_t)l * DM, h);

        mgemm_k<0, float><<<gFF, 256, GSMEM>>>(h, wgT + (size_t)l * IFF * DM,
                                               nullptr, nullptr, gt, ROWS, IFF, DM);
        mgemm_k<2, __half><<<gFF, 256, GSMEM>>>(h, wuT + (size_t)l * IFF * DM,
                                                nullptr, gt, up, ROWS, IFF, DM);
        mgemm_k<1, float><<<gDM, 256, GSMEM>>>(up, wdT + (size_t)l * DM * IFF,
                                               nullptr, nullptr, x, ROWS, DM, IFF);
    }

    rmsnorm_k<float><<<ROWS, 256>>>(x, lnf, (float*)d_out);
}

// round 10
// speedup vs baseline: 11.8203x; 3.2186x over previous
#include <cuda_runtime.h>
#include <cuda_fp16.h>
#include <math.h>
#include <stdint.h>

// Problem constants
#define BSZ 2
#define SEQ 2048
#define DM  896
#define NL  24
#define NHQ 14
#define NHKV 2
#define DH  64
#define IFF 4864
#define ROWS (BSZ*SEQ)          // 4096
#define QKD (NHQ*DH)            // 896
#define KVD (NHKV*DH)           // 128
#define QKVD (QKD + 2*KVD)      // 1152

// ---------------- scratch (device globals; no allocations allowed) ----------
__device__ float  g_x  [ROWS*DM];
__device__ __half g_h  [ROWS*DM];
__device__ float  g_qkv[(size_t)ROWS*QKVD];
__device__ __half g_ao [ROWS*QKD];
__device__ float  g_gate[(size_t)ROWS*IFF];
__device__ __half g_up  [(size_t)ROWS*IFF];
// transposed (K-major) weights in fp16
__device__ __half g_wqkvT[(size_t)NL*QKVD*DM];
__device__ __half g_woT  [(size_t)NL*DM*QKD];
__device__ __half g_wgT  [(size_t)NL*IFF*DM];
__device__ __half g_wuT  [(size_t)NL*IFF*DM];
__device__ __half g_wdT  [(size_t)NL*DM*IFF];
__device__ float  g_bqkv [NL*QKVD];

// ---------------- PTX helpers ----------------
__device__ __forceinline__ uint32_t smem_u32(const void* p) {
    uint32_t a;
    asm("{ .reg .u64 t; cvta.to.shared.u64 t, %1; cvt.u32.u64 %0, t; }" : "=r"(a) : "l"(p));
    return a;
}
__device__ __forceinline__ void cp_async16(uint32_t s, const void* g) {
    asm volatile("cp.async.cg.shared.global [%0], [%1], 16;\n" :: "r"(s), "l"(g));
}
__device__ __forceinline__ void cp_commit() { asm volatile("cp.async.commit_group;\n" ::: "memory"); }
template <int N>
__device__ __forceinline__ void cp_wait() { asm volatile("cp.async.wait_group %0;\n" :: "n"(N) : "memory"); }

__device__ __forceinline__ void mma16(float* c, const uint32_t* a, const uint32_t* b) {
    asm volatile(
        "mma.sync.aligned.m16n8k16.row.col.f32.f16.f16.f32 "
        "{%0,%1,%2,%3}, {%4,%5,%6,%7}, {%8,%9}, {%0,%1,%2,%3};"
        : "+f"(c[0]), "+f"(c[1]), "+f"(c[2]), "+f"(c[3])
        : "r"(a[0]), "r"(a[1]), "r"(a[2]), "r"(a[3]), "r"(b[0]), "r"(b[1]));
}
__device__ __forceinline__ uint32_t pack2(float a, float b) {
    __half2 h = __floats2half2_rn(a, b);
    return *(uint32_t*)&h;
}

// ---------------- elementwise copy ----------------
__global__ void copy_k(float* __restrict__ dst, const float* __restrict__ src, int n) {
    int i = blockIdx.x * blockDim.x + threadIdx.x;
    if (i < n) dst[i] = src[i];
}

// ---------------- bias pack: [bq | bk | bv] per layer ----------------
__global__ void biaspack_k(const float* __restrict__ bq, const float* __restrict__ bk,
                           const float* __restrict__ bv, float* __restrict__ out) {
    int i = blockIdx.x * blockDim.x + threadIdx.x;
    if (i >= NL * QKVD) return;
    int l = i / QKVD, c = i % QKVD;
    float v;
    if (c < QKD) v = bq[l * QKD + c];
    else if (c < QKD + KVD) v = bk[l * KVD + c - QKD];
    else v = bv[l * KVD + c - QKD - KVD];
    out[i] = v;
}

// ---------------- transpose + fp16 round: out[z][c][r] = h(in[z][r][c]) ----
__global__ __launch_bounds__(256) void transpose_k(const float* __restrict__ in,
                                                   __half* __restrict__ out,
                                                   int R, int C,
                                                   size_t inLS, size_t outLS) {
    __shared__ float t[32][33];
    const float* ip = in + (size_t)blockIdx.z * inLS;
    __half* op = out + (size_t)blockIdx.z * outLS;
    int r0 = blockIdx.y * 32, c0 = blockIdx.x * 32;
    int tx = threadIdx.x & 31, ty = threadIdx.x >> 5;
#pragma unroll
    for (int i = 0; i < 32; i += 8)
        t[ty + i][tx] = ip[(size_t)(r0 + ty + i) * C + c0 + tx];
    __syncthreads();
#pragma unroll
    for (int i = 0; i < 32; i += 8)
        op[(size_t)(c0 + ty + i) * R + r0 + tx] = __float2half_rn(t[tx][ty + i]);
}

// ---------------- RMSNorm (templated output type) ----------------
template <typename OT>
__global__ __launch_bounds__(256) void rmsnorm_k(const float* __restrict__ x,
                                                 const float* __restrict__ w,
                                                 OT* __restrict__ o) {
    int row = blockIdx.x;
    const float* xr = x + (size_t)row * DM;
    float s = 0.f;
    for (int i = threadIdx.x; i < DM; i += 256) { float v = xr[i]; s += v * v; }
    __shared__ float red[256];
    red[threadIdx.x] = s;
    __syncthreads();
    for (int st = 128; st > 0; st >>= 1) {
        if (threadIdx.x < st) red[threadIdx.x] += red[threadIdx.x + st];
        __syncthreads();
    }
    float r = rsqrtf(red[0] / (float)DM + 1e-6f);
    OT* orow = o + (size_t)row * DM;
    for (int i = threadIdx.x; i < DM; i += 256) {
        float v = xr[i] * r * w[i];
        orow[i] = (OT)v;
    }
}

// ---------------- fp16 mma GEMM: C[M,N] = A[M,K] @ Bt[N,K]^T ----------------
#define PH 40                     // halves per smem row
#define STG_H (128 * PH)          // halves per A (or B) stage
template <int EPI, typename CT>
__global__ __launch_bounds__(256, 2) void mgemm_k(const __half* __restrict__ A,
                                                  const __half* __restrict__ Bt,
                                                  const float* __restrict__ bias,
                                                  const float* __restrict__ G,
                                                  CT* __restrict__ C,
                                                  int M, int N, int K) {
    extern __shared__ __half smemh[];
    uint32_t sbase = smem_u32(smemh);

    int tid = threadIdx.x;
    int wid = tid >> 5;
    int lane = tid & 31;
    int gid = lane >> 2, t4 = lane & 3;
    int wm = wid & 1, wn = wid >> 1;
    int row0 = blockIdx.y * 128, col0 = blockIdx.x * 128;

    const int NK = K >> 5;
    float acc[4][4][4] = {};

    int lr = tid >> 2, lc = tid & 3;
    uint32_t loff = (uint32_t)(lr * PH + lc * 8) * 2;
    const __half* Ag  = A  + (size_t)(row0 + lr) * K + lc * 8;
    const __half* Bg  = Bt + (size_t)(col0 + lr) * K + lc * 8;
    const __half* Ag2 = Ag + 64 * K;
    const __half* Bg2 = Bg + 64 * K;
    uint32_t loff2 = loff + (uint32_t)(64 * PH) * 2;

#define PREFETCH(stg, k0)                                             \
    do {                                                              \
        uint32_t sa = sbase + (stg) * (2 * STG_H * 2);                \
        uint32_t sb = sa + STG_H * 2;                                 \
        cp_async16(sa + loff,  Ag  + (k0));                           \
        cp_async16(sa + loff2, Ag2 + (k0));                           \
        cp_async16(sb + loff,  Bg  + (k0));                           \
        cp_async16(sb + loff2, Bg2 + (k0));                           \
    } while (0)

    PREFETCH(0, 0); cp_commit();
    PREFETCH(1, 32); cp_commit();

    for (int kt = 0; kt < NK; kt++) {
        if (kt + 2 < NK) cp_wait<1>(); else cp_wait<0>();
        __syncthreads();
        if (kt + 2 < NK) {
            PREFETCH((kt + 2) % 3, (kt + 2) << 5);
            cp_commit();
        }
        int s = kt % 3;
        const __half* as = smemh + s * (2 * STG_H);
        const __half* bs = as + STG_H;
#pragma unroll
        for (int ks = 0; ks < 2; ks++) {
            int kc = ks * 16 + 2 * t4;
            uint32_t af[4][4];
#pragma unroll
            for (int mt = 0; mt < 4; mt++) {
                int row = wm * 64 + mt * 16 + gid;
                af[mt][0] = *(const uint32_t*)(as + row * PH + kc);
                af[mt][1] = *(const uint32_t*)(as + (row + 8) * PH + kc);
                af[mt][2] = *(const uint32_t*)(as + row * PH + kc + 8);
                af[mt][3] = *(const uint32_t*)(as + (row + 8) * PH + kc + 8);
            }
            uint32_t bf[4][2];
#pragma unroll
            for (int nt = 0; nt < 4; nt++) {
                int col = wn * 32 + nt * 8 + gid;
                bf[nt][0] = *(const uint32_t*)(bs + col * PH + kc);
                bf[nt][1] = *(const uint32_t*)(bs + col * PH + kc + 8);
            }
#pragma unroll
            for (int mt = 0; mt < 4; mt++)
#pragma unroll
                for (int nt = 0; nt < 4; nt++)
                    mma16(acc[mt][nt], af[mt], bf[nt]);
        }
    }
#undef PREFETCH

#pragma unroll
    for (int mt = 0; mt < 4; mt++) {
#pragma unroll
        for (int nt = 0; nt < 4; nt++) {
            int rg = row0 + wm * 64 + mt * 16 + gid;
            int cg = col0 + wn * 32 + nt * 8 + 2 * t4;
#pragma unroll
            for (int half = 0; half < 2; half++) {
                int r = rg + half * 8;
                float v0 = acc[mt][nt][half * 2 + 0];
                float v1 = acc[mt][nt][half * 2 + 1];
                size_t idx = (size_t)r * N + cg;
                if (EPI == 0) {
                    float b0 = bias ? bias[cg] : 0.f;
                    float b1 = bias ? bias[cg + 1] : 0.f;
                    *(float2*)((float*)C + idx) = make_float2(v0 + b0, v1 + b1);
                } else if (EPI == 1) {
                    float2 o = *(float2*)((float*)C + idx);
                    o.x += v0; o.y += v1;
                    *(float2*)((float*)C + idx) = o;
                } else {
                    float g0 = G[idx], g1 = G[idx + 1];
                    __half2 hv = __floats2half2_rn(v0 * (g0 / (1.f + expf(-g0))),
                                                   v1 * (g1 / (1.f + expf(-g1))));
                    *(__half2*)((__half*)C + idx) = hv;
                }
            }
        }
    }
}

// ---------------- RoPE on packed qkv (q heads 0-13, k heads 14-15) ----------
__global__ void rope_k(float* __restrict__ p) {
    int row = blockIdx.x;
    int s = row & (SEQ - 1);
    int t = threadIdx.x;
    int h = t >> 5, i = t & 31;
    float inv = 1.0f / powf(1.0e6f, (float)i / 32.0f);
    float ang = (float)s * inv;
    float c = cosf(ang), sn = sinf(ang);
    float* base = p + (size_t)row * QKVD + h * 64;
    float x1 = base[i], x2 = base[i + 32];
    base[i]      = x1 * c - x2 * sn;
    base[i + 32] = x2 * c + x1 * sn;
}

// ---------------- Attention: FA2-style tensor-core kernel -------------------
// 256 threads (8 warps), 128 queries/block (16/warp), K-tile 64.
// grid (SEQ/128, NHQ, BSZ).
#define PKH 72
__global__ __launch_bounds__(256) void attn_k(const float* __restrict__ qkv,
                                              const int* __restrict__ tt,
                                              const float* __restrict__ am,
                                              __half* __restrict__ out) {
    __shared__ __half Ks [64][PKH];     // [key][d]
    __shared__ __half VsT[64][PKH];     // [d][key]
    __shared__ __half qsh[128][PKH];    // [q][d]
    __shared__ int    tts[64];
    __shared__ float  padf[64];

    int b = blockIdx.z, h = blockIdx.y;
    int tid = threadIdx.x;
    int w = tid >> 5;
    int lane = tid & 31;
    int gid = lane >> 2, t4 = lane & 3;
    int qt0 = blockIdx.x * 128;
    int kvh = h / (NHQ / NHKV);
    int bS = b * SEQ;
    const float NEG = -3.0e38f;
    const float scale = 0.125f;

    // ---- load Q tile (fp32 -> fp16 smem) ----
    for (int idx = tid; idx < 128 * 16; idx += 256) {
        int r = idx >> 4, c4 = (idx & 15) * 4;
        float4 qv = *(const float4*)(qkv + (size_t)(bS + qt0 + r) * QKVD + h * 64 + c4);
        *(__half2*)&qsh[r][c4]     = __floats2half2_rn(qv.x, qv.y);
        *(__half2*)&qsh[r][c4 + 2] = __floats2half2_rn(qv.z, qv.w);
    }
    __syncthreads();

    // ---- Q fragments in registers (whole kernel) ----
    int qb = w * 16;
    uint32_t qf[4][4];
#pragma unroll
    for (int kc = 0; kc < 4; kc++) {
        int k0 = kc * 16 + 2 * t4;
        qf[kc][0] = *(const uint32_t*)&qsh[qb + gid][k0];
        qf[kc][1] = *(const uint32_t*)&qsh[qb + gid + 8][k0];
        qf[kc][2] = *(const uint32_t*)&qsh[qb + gid][k0 + 8];
        qf[kc][3] = *(const uint32_t*)&qsh[qb + gid + 8][k0 + 8];
    }

    int qi0 = qt0 + qb + gid, qi1 = qi0 + 8;
    int tq0 = tt[bS + qi0], tq1 = tt[bS + qi1];

    float m0 = -INFINITY, m1 = -INFINITY, l0 = 0.f, l1 = 0.f;
    float o[8][4];
#pragma unroll
    for (int dt = 0; dt < 8; dt++) { o[dt][0] = 0.f; o[dt][1] = 0.f; o[dt][2] = 0.f; o[dt][3] = 0.f; }

    for (int kt = 0; kt < SEQ; kt += 64) {
        __syncthreads();
        // K tile: [key][d] fp16
        for (int idx = tid; idx < 64 * 16; idx += 256) {
            int r = idx >> 4, c4 = (idx & 15) * 4;
            float4 kv = *(const float4*)(qkv + (size_t)(bS + kt + r) * QKVD + QKD + kvh * 64 + c4);
            *(__half2*)&Ks[r][c4]     = __floats2half2_rn(kv.x, kv.y);
            *(__half2*)&Ks[r][c4 + 2] = __floats2half2_rn(kv.z, kv.w);
        }
        // V tile transposed: [d][key] fp16, key-pairs packed as half2
        for (int idx = tid; idx < 32 * 16; idx += 256) {
            int rp = idx >> 4, c4 = (idx & 15) * 4;
            int r = rp * 2;
            const float* vb = qkv + (size_t)(bS + kt + r) * QKVD + QKD + KVD + kvh * 64;
            float4 va = *(const float4*)(vb + c4);
            float4 vc = *(const float4*)(vb + QKVD + c4);
            *(__half2*)&VsT[c4 + 0][r] = __floats2half2_rn(va.x, vc.x);
            *(__half2*)&VsT[c4 + 1][r] = __floats2half2_rn(va.y, vc.y);
            *(__half2*)&VsT[c4 + 2][r] = __floats2half2_rn(va.z, vc.z);
            *(__half2*)&VsT[c4 + 3][r] = __floats2half2_rn(va.w, vc.w);
        }
        if (tid < 64) {
            tts[tid]  = tt[bS + kt + tid];
            padf[tid] = (1.f - am[bS + kt + tid]) * NEG;
        }
        __syncthreads();

        // ---- QK^T ----
        float sc[8][4];
#pragma unroll
        for (int nt = 0; nt < 8; nt++) { sc[nt][0] = 0.f; sc[nt][1] = 0.f; sc[nt][2] = 0.f; sc[nt][3] = 0.f; }
#pragma unroll
        for (int kc = 0; kc < 4; kc++) {
            int k0 = kc * 16 + 2 * t4;
#pragma unroll
            for (int nt = 0; nt < 8; nt++) {
                uint32_t bf[2];
                bf[0] = *(const uint32_t*)&Ks[nt * 8 + gid][k0];
                bf[1] = *(const uint32_t*)&Ks[nt * 8 + gid][k0 + 8];
                mma16(sc[nt], qf[kc], bf);
            }
        }

        // ---- mask + bias + row max ----
        float rx0 = -INFINITY, rx1 = -INFINITY;
#pragma unroll
        for (int nt = 0; nt < 8; nt++) {
            int c0 = nt * 8 + 2 * t4, c1 = c0 + 1;
            int tk0 = tts[c0], tk1 = tts[c1];
            float pd0 = padf[c0], pd1 = padf[c1];
            int ki0 = kt + c0, ki1 = kt + c1;
            bool a00 = (tq0 == 0) ? (tk0 == 0) : ((tk0 == 0) || (ki0 <= qi0));
            bool a01 = (tq0 == 0) ? (tk1 == 0) : ((tk1 == 0) || (ki1 <= qi0));
            bool a10 = (tq1 == 0) ? (tk0 == 0) : ((tk0 == 0) || (ki0 <= qi1));
            bool a11 = (tq1 == 0) ? (tk1 == 0) : ((tk1 == 0) || (ki1 <= qi1));
            sc[nt][0] = fmaxf(sc[nt][0] * scale + (a00 ? 0.f : NEG) + pd0, -3.3e38f);
            sc[nt][1] = fmaxf(sc[nt][1] * scale + (a01 ? 0.f : NEG) + pd1, -3.3e38f);
            sc[nt][2] = fmaxf(sc[nt][2] * scale + (a10 ? 0.f : NEG) + pd0, -3.3e38f);
            sc[nt][3] = fmaxf(sc[nt][3] * scale + (a11 ? 0.f : NEG) + pd1, -3.3e38f);
            rx0 = fmaxf(rx0, fmaxf(sc[nt][0], sc[nt][1]));
            rx1 = fmaxf(rx1, fmaxf(sc[nt][2], sc[nt][3]));
        }
        rx0 = fmaxf(rx0, __shfl_xor_sync(0xffffffffu, rx0, 1));
        rx0 = fmaxf(rx0, __shfl_xor_sync(0xffffffffu, rx0, 2));
        rx1 = fmaxf(rx1, __shfl_xor_sync(0xffffffffu, rx1, 1));
        rx1 = fmaxf(rx1, __shfl_xor_sync(0xffffffffu, rx1, 2));

        float mn0 = fmaxf(m0, rx0), mn1 = fmaxf(m1, rx1);
        float corr0 = __expf(m0 - mn0), corr1 = __expf(m1 - mn1);

        // ---- exponentiate + row sums ----
        float rs0 = 0.f, rs1 = 0.f;
#pragma unroll
        for (int nt = 0; nt < 8; nt++) {
            sc[nt][0] = __expf(sc[nt][0] - mn0);
            sc[nt][1] = __expf(sc[nt][1] - mn0);
            sc[nt][2] = __expf(sc[nt][2] - mn1);
            sc[nt][3] = __expf(sc[nt][3] - mn1);
            rs0 += sc[nt][0] + sc[nt][1];
            rs1 += sc[nt][2] + sc[nt][3];
        }
        rs0 += __shfl_xor_sync(0xffffffffu, rs0, 1);
        rs0 += __shfl_xor_sync(0xffffffffu, rs0, 2);
        rs1 += __shfl_xor_sync(0xffffffffu, rs1, 1);
        rs1 += __shfl_xor_sync(0xffffffffu, rs1, 2);
        l0 = l0 * corr0 + rs0;
        l1 = l1 * corr1 + rs1;
        m0 = mn0; m1 = mn1;

        // ---- rescale O, pack P fragments (register-only), PV ----
#pragma unroll
        for (int dt = 0; dt < 8; dt++) {
            o[dt][0] *= corr0; o[dt][1] *= corr0;
            o[dt][2] *= corr1; o[dt][3] *= corr1;
        }
        uint32_t pf[4][4];
#pragma unroll
        for (int kc = 0; kc < 4; kc++) {
            pf[kc][0] = pack2(sc[2 * kc][0], sc[2 * kc][1]);
            pf[kc][1] = pack2(sc[2 * kc][2], sc[2 * kc][3]);
            pf[kc][2] = pack2(sc[2 * kc + 1][0], sc[2 * kc + 1][1]);
            pf[kc][3] = pack2(sc[2 * kc + 1][2], sc[2 * kc + 1][3]);
        }
#pragma unroll
        for (int kc = 0; kc < 4; kc++) {
            int k0 = kc * 16 + 2 * t4;
#pragma unroll
            for (int dt = 0; dt < 8; dt++) {
                uint32_t bf[2];
                bf[0] = *(const uint32_t*)&VsT[dt * 8 + gid][k0];
                bf[1] = *(const uint32_t*)&VsT[dt * 8 + gid][k0 + 8];
                mma16(o[dt], pf[kc], bf);
            }
        }
    }

    // ---- epilogue ----
    float il0 = 1.0f / l0, il1 = 1.0f / l1;
    __half* r0p = out + (size_t)(bS + qi0) * QKD + h * 64;
    __half* r1p = out + (size_t)(bS + qi1) * QKD + h * 64;
#pragma unroll
    for (int dt = 0; dt < 8; dt++) {
        int d0 = dt * 8 + 2 * t4;
        *(__half2*)(r0p + d0) = __floats2half2_rn(o[dt][0] * il0, o[dt][1] * il0);
        *(__half2*)(r1p + d0) = __floats2half2_rn(o[dt][2] * il1, o[dt][3] * il1);
    }
}

// ---------------- host driver ----------------
extern "C" void kernel_launch(void* const* d_in, const int* in_sizes, int n_in,
                              void* d_out, int out_size) {
    const float* emb = (const float*)d_in[0];
    const int*   tt  = (const int*)  d_in[1];
    const float* am  = (const float*)d_in[2];
    const float* wq  = (const float*)d_in[3];
    const float* bq  = (const float*)d_in[4];
    const float* wk  = (const float*)d_in[5];
    const float* bk  = (const float*)d_in[6];
    const float* wv  = (const float*)d_in[7];
    const float* bv  = (const float*)d_in[8];
    const float* wo  = (const float*)d_in[9];
    const float* wg  = (const float*)d_in[10];
    const float* wu  = (const float*)d_in[11];
    const float* wd  = (const float*)d_in[12];
    const float* ln1 = (const float*)d_in[13];
    const float* ln2 = (const float*)d_in[14];
    const float* lnf = (const float*)d_in[15];

    float *x, *qkv, *gt, *bqkv;
    __half *h, *ao, *up, *wqkvT, *woT, *wgT, *wuT, *wdT;
    cudaGetSymbolAddress((void**)&x,   g_x);
    cudaGetSymbolAddress((void**)&h,   g_h);
    cudaGetSymbolAddress((void**)&qkv, g_qkv);
    cudaGetSymbolAddress((void**)&ao,  g_ao);
    cudaGetSymbolAddress((void**)&gt,  g_gate);
    cudaGetSymbolAddress((void**)&up,  g_up);
    cudaGetSymbolAddress((void**)&wqkvT, g_wqkvT);
    cudaGetSymbolAddress((void**)&woT, g_woT);
    cudaGetSymbolAddress((void**)&wgT, g_wgT);
    cudaGetSymbolAddress((void**)&wuT, g_wuT);
    cudaGetSymbolAddress((void**)&wdT, g_wdT);
    cudaGetSymbolAddress((void**)&bqkv, g_bqkv);

    const int GSMEM = 3 * 2 * STG_H * 2;   // 61440 bytes
    cudaFuncSetAttribute(mgemm_k<0, float>,  cudaFuncAttributeMaxDynamicSharedMemorySize, GSMEM);
    cudaFuncSetAttribute(mgemm_k<1, float>,  cudaFuncAttributeMaxDynamicSharedMemorySize, GSMEM);
    cudaFuncSetAttribute(mgemm_k<2, __half>, cudaFuncAttributeMaxDynamicSharedMemorySize, GSMEM);

    // weight transposes (+fp16 rounding); qkv packed into [q|k|v] rows
    size_t oLS = (size_t)QKVD * DM;
    transpose_k<<<dim3(QKD/32, DM/32, NL), 256>>>(wq, wqkvT,            DM, QKD, (size_t)DM*QKD, oLS);
    transpose_k<<<dim3(KVD/32, DM/32, NL), 256>>>(wk, wqkvT + (size_t)QKD*DM,       DM, KVD, (size_t)DM*KVD, oLS);
    transpose_k<<<dim3(KVD/32, DM/32, NL), 256>>>(wv, wqkvT + (size_t)(QKD+KVD)*DM, DM, KVD, (size_t)DM*KVD, oLS);
    transpose_k<<<dim3(DM/32, QKD/32, NL), 256>>>(wo, woT, QKD, DM, (size_t)QKD*DM, (size_t)DM*QKD);
    transpose_k<<<dim3(IFF/32, DM/32, NL), 256>>>(wg, wgT, DM, IFF, (size_t)DM*IFF, (size_t)IFF*DM);
    transpose_k<<<dim3(IFF/32, DM/32, NL), 256>>>(wu, wuT, DM, IFF, (size_t)DM*IFF, (size_t)IFF*DM);
    transpose_k<<<dim3(DM/32, IFF/32, NL), 256>>>(wd, wdT, IFF, DM, (size_t)IFF*DM, (size_t)DM*IFF);
    biaspack_k<<<(NL*QKVD + 255)/256, 256>>>(bq, bk, bv, bqkv);

    int nx = ROWS * DM;
    copy_k<<<(nx + 255) / 256, 256>>>(x, emb, nx);

    dim3 gQKV(QKVD / 128, ROWS / 128);   // (9, 32)
    dim3 gDM (DM   / 128, ROWS / 128);   // (7, 32)
    dim3 gFF (IFF  / 128, ROWS / 128);   // (38, 32)
    dim3 gAt (SEQ / 128, NHQ, BSZ);      // (16, 14, 2)

    for (int l = 0; l < NL; l++) {
        rmsnorm_k<__half><<<ROWS, 256>>>(x, ln1 + (size_t)l * DM, h);

        mgemm_k<0, float><<<gQKV, 256, GSMEM>>>(h, wqkvT + (size_t)l * QKVD * DM,
                                                bqkv + (size_t)l * QKVD, nullptr, qkv,
                                                ROWS, QKVD, DM);

        rope_k<<<ROWS, 16 * 32>>>(qkv);

        attn_k<<<gAt, 256>>>(qkv, tt, am, ao);

        mgemm_k<1, float><<<gDM, 256, GSMEM>>>(ao, woT + (size_t)l * DM * QKD,
                                               nullptr, nullptr, x, ROWS, DM, QKD);

        rmsnorm_k<__half><<<ROWS, 256>>>(x, ln2 + (size_t)l * DM, h);

        mgemm_k<0, float><<<gFF, 256, GSMEM>>>(h, wgT + (size_t)l * IFF * DM,
                                               nullptr, nullptr, gt, ROWS, IFF, DM);
        mgemm_k<2, __half><<<gFF, 256, GSMEM>>>(h, wuT + (size_t)l * IFF * DM,
                                                nullptr, gt, up, ROWS, IFF, DM);
        mgemm_k<1, float><<<gDM, 256, GSMEM>>>(up, wdT + (size_t)l * DM * IFF,
                                               nullptr, nullptr, x, ROWS, DM, IFF);
    }

    rmsnorm_k<float><<<ROWS, 256>>>(x, lnf, (float*)d_out);
}

// round 12
// speedup vs baseline: 13.7393x; 1.1623x over previous
#include <cuda_runtime.h>
#include <cuda_fp16.h>
#include <math.h>
#include <stdint.h>

// Problem constants
#define BSZ 2
#define SEQ 2048
#define DM  896
#define NL  24
#define NHQ 14
#define NHKV 2
#define DH  64
#define IFF 4864
#define ROWS (BSZ*SEQ)          // 4096
#define QKD (NHQ*DH)            // 896
#define KVD (NHKV*DH)           // 128
#define QKVD (QKD + 2*KVD)      // 1152

// ---------------- scratch (device globals; no allocations allowed) ----------
__device__ float  g_x  [ROWS*DM];
__device__ __half g_h  [ROWS*DM];
__device__ float  g_qkv[(size_t)ROWS*QKVD];
__device__ __half g_ao [ROWS*QKD];
__device__ __half g_gate[(size_t)ROWS*IFF];
__device__ __half g_up  [(size_t)ROWS*IFF];
// transposed (K-major) weights in fp16
__device__ __half g_wqkvT[(size_t)NL*QKVD*DM];
__device__ __half g_woT  [(size_t)NL*DM*QKD];
__device__ __half g_wgT  [(size_t)NL*IFF*DM];
__device__ __half g_wuT  [(size_t)NL*IFF*DM];
__device__ __half g_wdT  [(size_t)NL*DM*IFF];
__device__ float  g_bqkv [NL*QKVD];

// ---------------- PTX helpers ----------------
__device__ __forceinline__ uint32_t smem_u32(const void* p) {
    uint32_t a;
    asm("{ .reg .u64 t; cvta.to.shared.u64 t, %1; cvt.u32.u64 %0, t; }" : "=r"(a) : "l"(p));
    return a;
}
__device__ __forceinline__ void cp_async16(uint32_t s, const void* g) {
    asm volatile("cp.async.cg.shared.global [%0], [%1], 16;\n" :: "r"(s), "l"(g));
}
__device__ __forceinline__ void cp_commit() { asm volatile("cp.async.commit_group;\n" ::: "memory"); }
template <int N>
__device__ __forceinline__ void cp_wait() { asm volatile("cp.async.wait_group %0;\n" :: "n"(N) : "memory"); }

__device__ __forceinline__ void mma16(float* c, const uint32_t* a, const uint32_t* b) {
    asm volatile(
        "mma.sync.aligned.m16n8k16.row.col.f32.f16.f16.f32 "
        "{%0,%1,%2,%3}, {%4,%5,%6,%7}, {%8,%9}, {%0,%1,%2,%3};"
        : "+f"(c[0]), "+f"(c[1]), "+f"(c[2]), "+f"(c[3])
        : "r"(a[0]), "r"(a[1]), "r"(a[2]), "r"(a[3]), "r"(b[0]), "r"(b[1]));
}
__device__ __forceinline__ void ldsm4(uint32_t* r, uint32_t addr) {
    asm volatile("ldmatrix.sync.aligned.m8n8.x4.shared.b16 {%0,%1,%2,%3}, [%4];"
        : "=r"(r[0]), "=r"(r[1]), "=r"(r[2]), "=r"(r[3]) : "r"(addr));
}
__device__ __forceinline__ uint32_t pack2(float a, float b) {
    __half2 h = __floats2half2_rn(a, b);
    return *(uint32_t*)&h;
}

// ---------------- elementwise copy ----------------
__global__ void copy_k(float* __restrict__ dst, const float* __restrict__ src, int n) {
    int i = blockIdx.x * blockDim.x + threadIdx.x;
    if (i < n) dst[i] = src[i];
}

// ---------------- bias pack: [bq | bk | bv] per layer ----------------
__global__ void biaspack_k(const float* __restrict__ bq, const float* __restrict__ bk,
                           const float* __restrict__ bv, float* __restrict__ out) {
    int i = blockIdx.x * blockDim.x + threadIdx.x;
    if (i >= NL * QKVD) return;
    int l = i / QKVD, c = i % QKVD;
    float v;
    if (c < QKD) v = bq[l * QKD + c];
    else if (c < QKD + KVD) v = bk[l * KVD + c - QKD];
    else v = bv[l * KVD + c - QKD - KVD];
    out[i] = v;
}

// ---------------- transpose + fp16 round: out[z][c][r] = h(in[z][r][c]) ----
__global__ __launch_bounds__(256) void transpose_k(const float* __restrict__ in,
                                                   __half* __restrict__ out,
                                                   int R, int C,
                                                   size_t inLS, size_t outLS) {
    __shared__ float t[32][33];
    const float* ip = in + (size_t)blockIdx.z * inLS;
    __half* op = out + (size_t)blockIdx.z * outLS;
    int r0 = blockIdx.y * 32, c0 = blockIdx.x * 32;
    int tx = threadIdx.x & 31, ty = threadIdx.x >> 5;
#pragma unroll
    for (int i = 0; i < 32; i += 8)
        t[ty + i][tx] = ip[(size_t)(r0 + ty + i) * C + c0 + tx];
    __syncthreads();
#pragma unroll
    for (int i = 0; i < 32; i += 8)
        op[(size_t)(c0 + ty + i) * R + r0 + tx] = __float2half_rn(t[tx][ty + i]);
}

// ---------------- RMSNorm (templated output type) ----------------
template <typename OT>
__global__ __launch_bounds__(256) void rmsnorm_k(const float* __restrict__ x,
                                                 const float* __restrict__ w,
                                                 OT* __restrict__ o) {
    int row = blockIdx.x;
    const float* xr = x + (size_t)row * DM;
    float s = 0.f;
    for (int i = threadIdx.x; i < DM; i += 256) { float v = xr[i]; s += v * v; }
    __shared__ float red[256];
    red[threadIdx.x] = s;
    __syncthreads();
    for (int st = 128; st > 0; st >>= 1) {
        if (threadIdx.x < st) red[threadIdx.x] += red[threadIdx.x + st];
        __syncthreads();
    }
    float r = rsqrtf(red[0] / (float)DM + 1e-6f);
    OT* orow = o + (size_t)row * DM;
    for (int i = threadIdx.x; i < DM; i += 256) {
        float v = xr[i] * r * w[i];
        orow[i] = (OT)v;
    }
}

// ---------------- fp16 mma GEMM: C[M,N] = A[M,K] @ Bt[N,K]^T ----------------
// EPI 0: C = acc + bias (CT float or half) ; EPI 1: C(f32) += acc ;
// EPI 2: C(f16) = h(silu(G) * acc), G fp16
#define PH 40                     // halves per smem row
#define STG_H (128 * PH)          // halves per A (or B) stage
template <int EPI, typename CT>
__global__ __launch_bounds__(256, 2) void mgemm_k(const __half* __restrict__ A,
                                                  const __half* __restrict__ Bt,
                                                  const float* __restrict__ bias,
                                                  const __half* __restrict__ G,
                                                  CT* __restrict__ C,
                                                  int M, int N, int K) {
    extern __shared__ __half smemh[];
    uint32_t sbase = smem_u32(smemh);

    int tid = threadIdx.x;
    int wid = tid >> 5;
    int lane = tid & 31;
    int gid = lane >> 2, t4 = lane & 3;
    int wm = wid & 1, wn = wid >> 1;
    int row0 = blockIdx.y * 128, col0 = blockIdx.x * 128;

    const int NK = K >> 5;
    float acc[4][4][4] = {};

    // ldmatrix lane offsets (bytes)
    uint32_t aoff[4];
#pragma unroll
    for (int mt = 0; mt < 4; mt++)
        aoff[mt] = (uint32_t)(((wm * 64 + mt * 16 + (lane & 15)) * PH
                               + ((lane >> 4) * 8)) * 2);
    uint32_t boff[2];
#pragma unroll
    for (int j = 0; j < 2; j++)
        boff[j] = (uint32_t)(((wn * 32 + j * 16 + (lane & 7) + ((lane & 16) ? 8 : 0)) * PH
                              + (((lane >> 3) & 1) * 8)) * 2);

    // cp.async load coords
    int lr = tid >> 2, lc = tid & 3;
    uint32_t loff = (uint32_t)(lr * PH + lc * 8) * 2;
    const __half* Ag  = A  + (size_t)(row0 + lr) * K + lc * 8;
    const __half* Bg  = Bt + (size_t)(col0 + lr) * K + lc * 8;
    const __half* Ag2 = Ag + 64 * K;
    const __half* Bg2 = Bg + 64 * K;
    uint32_t loff2 = loff + (uint32_t)(64 * PH) * 2;

#define PREFETCH(stg, k0)                                             \
    do {                                                              \
        uint32_t sa = sbase + (stg) * (2 * STG_H * 2);                \
        uint32_t sb = sa + STG_H * 2;                                 \
        cp_async16(sa + loff,  Ag  + (k0));                           \
        cp_async16(sa + loff2, Ag2 + (k0));                           \
        cp_async16(sb + loff,  Bg  + (k0));                           \
        cp_async16(sb + loff2, Bg2 + (k0));                           \
    } while (0)

    PREFETCH(0, 0); cp_commit();
    PREFETCH(1, 32); cp_commit();

    for (int kt = 0; kt < NK; kt++) {
        if (kt + 2 < NK) cp_wait<1>(); else cp_wait<0>();
        __syncthreads();
        if (kt + 2 < NK) {
            PREFETCH((kt + 2) % 3, (kt + 2) << 5);
            cp_commit();
        }
        int s = kt % 3;
        uint32_t sa = sbase + s * (2 * STG_H * 2);
        uint32_t sb = sa + STG_H * 2;
#pragma unroll
        for (int ks = 0; ks < 2; ks++) {
            uint32_t ko = ks * 32;   // 16 halves
            uint32_t af[4][4];
#pragma unroll
            for (int mt = 0; mt < 4; mt++)
                ldsm4(af[mt], sa + aoff[mt] + ko);
            uint32_t bq0[4], bq1[4];
            ldsm4(bq0, sb + boff[0] + ko);
            ldsm4(bq1, sb + boff[1] + ko);
#pragma unroll
            for (int mt = 0; mt < 4; mt++) {
                mma16(acc[mt][0], af[mt], &bq0[0]);
                mma16(acc[mt][1], af[mt], &bq0[2]);
                mma16(acc[mt][2], af[mt], &bq1[0]);
                mma16(acc[mt][3], af[mt], &bq1[2]);
            }
        }
    }
#undef PREFETCH

#pragma unroll
    for (int mt = 0; mt < 4; mt++) {
#pragma unroll
        for (int nt = 0; nt < 4; nt++) {
            int rg = row0 + wm * 64 + mt * 16 + gid;
            int cg = col0 + wn * 32 + nt * 8 + 2 * t4;
#pragma unroll
            for (int half = 0; half < 2; half++) {
                int r = rg + half * 8;
                float v0 = acc[mt][nt][half * 2 + 0];
                float v1 = acc[mt][nt][half * 2 + 1];
                size_t idx = (size_t)r * N + cg;
                if (EPI == 0) {
                    float b0 = bias ? bias[cg] : 0.f;
                    float b1 = bias ? bias[cg + 1] : 0.f;
                    if (sizeof(CT) == 2) {
                        __half2 hv = __floats2half2_rn(v0 + b0, v1 + b1);
                        *(__half2*)((__half*)C + idx) = hv;
                    } else {
                        *(float2*)((float*)C + idx) = make_float2(v0 + b0, v1 + b1);
                    }
                } else if (EPI == 1) {
                    float2 o = *(float2*)((float*)C + idx);
                    o.x += v0; o.y += v1;
                    *(float2*)((float*)C + idx) = o;
                } else {
                    float g0 = __half2float(G[idx]);
                    float g1 = __half2float(G[idx + 1]);
                    __half2 hv = __floats2half2_rn(v0 * (g0 / (1.f + expf(-g0))),
                                                   v1 * (g1 / (1.f + expf(-g1))));
                    *(__half2*)((__half*)C + idx) = hv;
                }
            }
        }
    }
}

// ---------------- RoPE on packed qkv (q heads 0-13, k heads 14-15) ----------
__global__ void rope_k(float* __restrict__ p) {
    int row = blockIdx.x;
    int s = row & (SEQ - 1);
    int t = threadIdx.x;
    int h = t >> 5, i = t & 31;
    float inv = 1.0f / powf(1.0e6f, (float)i / 32.0f);
    float ang = (float)s * inv;
    float c = cosf(ang), sn = sinf(ang);
    float* base = p + (size_t)row * QKVD + h * 64;
    float x1 = base[i], x2 = base[i + 32];
    base[i]      = x1 * c - x2 * sn;
    base[i + 32] = x2 * c + x1 * sn;
}

// ---------------- Attention: FA2-style tensor-core kernel -------------------
// 256 threads (8 warps), 128 queries/block (16/warp), K-tile 64.
// grid (SEQ/128, NHQ, BSZ).
#define PKH 72
__global__ __launch_bounds__(256) void attn_k(const float* __restrict__ qkv,
                                              const int* __restrict__ tt,
                                              const float* __restrict__ am,
                                              __half* __restrict__ out) {
    __shared__ __half Ks [64][PKH];     // [key][d]
    __shared__ __half VsT[64][PKH];     // [d][key]
    __shared__ __half qsh[128][PKH];    // [q][d]
    __shared__ int    tts[64];
    __shared__ float  padf[64];

    int b = blockIdx.z, h = blockIdx.y;
    int tid = threadIdx.x;
    int w = tid >> 5;
    int lane = tid & 31;
    int gid = lane >> 2, t4 = lane & 3;
    int qt0 = blockIdx.x * 128;
    int kvh = h / (NHQ / NHKV);
    int bS = b * SEQ;
    const float NEG = -3.0e38f;
    const float scale = 0.125f;

    uint32_t ksb = smem_u32(&Ks[0][0]);
    uint32_t vsb = smem_u32(&VsT[0][0]);
    // ldmatrix B-operand lane offset (shared by K and V tiles), bytes
    uint32_t lboff[4];
#pragma unroll
    for (int j = 0; j < 4; j++)
        lboff[j] = (uint32_t)(((j * 16 + (lane & 7) + ((lane & 16) ? 8 : 0)) * PKH
                               + (((lane >> 3) & 1) * 8)) * 2);

    // ---- load Q tile (fp32 -> fp16 smem) ----
    for (int idx = tid; idx < 128 * 16; idx += 256) {
        int r = idx >> 4, c4 = (idx & 15) * 4;
        float4 qv = *(const float4*)(qkv + (size_t)(bS + qt0 + r) * QKVD + h * 64 + c4);
        *(__half2*)&qsh[r][c4]     = __floats2half2_rn(qv.x, qv.y);
        *(__half2*)&qsh[r][c4 + 2] = __floats2half2_rn(qv.z, qv.w);
    }
    __syncthreads();

    // ---- Q fragments in registers (whole kernel) ----
    int qb = w * 16;
    uint32_t qf[4][4];
#pragma unroll
    for (int kc = 0; kc < 4; kc++) {
        int k0 = kc * 16 + 2 * t4;
        qf[kc][0] = *(const uint32_t*)&qsh[qb + gid][k0];
        qf[kc][1] = *(const uint32_t*)&qsh[qb + gid + 8][k0];
        qf[kc][2] = *(const uint32_t*)&qsh[qb + gid][k0 + 8];
        qf[kc][3] = *(const uint32_t*)&qsh[qb + gid + 8][k0 + 8];
    }

    int qi0 = qt0 + qb + gid, qi1 = qi0 + 8;
    int tq0 = tt[bS + qi0], tq1 = tt[bS + qi1];

    float m0 = -INFINITY, m1 = -INFINITY, l0 = 0.f, l1 = 0.f;
    float o[8][4];
#pragma unroll
    for (int dt = 0; dt < 8; dt++) { o[dt][0] = 0.f; o[dt][1] = 0.f; o[dt][2] = 0.f; o[dt][3] = 0.f; }

    for (int kt = 0; kt < SEQ; kt += 64) {
        __syncthreads();
        // K tile: [key][d] fp16
        for (int idx = tid; idx < 64 * 16; idx += 256) {
            int r = idx >> 4, c4 = (idx & 15) * 4;
            float4 kv = *(const float4*)(qkv + (size_t)(bS + kt + r) * QKVD + QKD + kvh * 64 + c4);
            *(__half2*)&Ks[r][c4]     = __floats2half2_rn(kv.x, kv.y);
            *(__half2*)&Ks[r][c4 + 2] = __floats2half2_rn(kv.z, kv.w);
        }
        // V tile transposed: [d][key] fp16, key-pairs packed as half2
        for (int idx = tid; idx < 32 * 16; idx += 256) {
            int rp = idx >> 4, c4 = (idx & 15) * 4;
            int r = rp * 2;
            const float* vb = qkv + (size_t)(bS + kt + r) * QKVD + QKD + KVD + kvh * 64;
            float4 va = *(const float4*)(vb + c4);
            float4 vc = *(const float4*)(vb + QKVD + c4);
            *(__half2*)&VsT[c4 + 0][r] = __floats2half2_rn(va.x, vc.x);
            *(__half2*)&VsT[c4 + 1][r] = __floats2half2_rn(va.y, vc.y);
            *(__half2*)&VsT[c4 + 2][r] = __floats2half2_rn(va.z, vc.z);
            *(__half2*)&VsT[c4 + 3][r] = __floats2half2_rn(va.w, vc.w);
        }
        if (tid < 64) {
            tts[tid]  = tt[bS + kt + tid];
            padf[tid] = (1.f - am[bS + kt + tid]) * NEG;
        }
        __syncthreads();

        // ---- QK^T (ldmatrix) ----
        float sc[8][4];
#pragma unroll
        for (int nt = 0; nt < 8; nt++) { sc[nt][0] = 0.f; sc[nt][1] = 0.f; sc[nt][2] = 0.f; sc[nt][3] = 0.f; }
#pragma unroll
        for (int kc = 0; kc < 4; kc++) {
            uint32_t ko = kc * 32;
            uint32_t kq[4][4];
#pragma unroll
            for (int j = 0; j < 4; j++)
                ldsm4(kq[j], ksb + lboff[j] + ko);
#pragma unroll
            for (int j = 0; j < 4; j++) {
                mma16(sc[2 * j],     qf[kc], &kq[j][0]);
                mma16(sc[2 * j + 1], qf[kc], &kq[j][2]);
            }
        }

        // ---- mask + bias + row max ----
        float rx0 = -INFINITY, rx1 = -INFINITY;
#pragma unroll
        for (int nt = 0; nt < 8; nt++) {
            int c0 = nt * 8 + 2 * t4, c1 = c0 + 1;
            int tk0 = tts[c0], tk1 = tts[c1];
            float pd0 = padf[c0], pd1 = padf[c1];
            int ki0 = kt + c0, ki1 = kt + c1;
            bool a00 = (tq0 == 0) ? (tk0 == 0) : ((tk0 == 0) || (ki0 <= qi0));
            bool a01 = (tq0 == 0) ? (tk1 == 0) : ((tk1 == 0) || (ki1 <= qi0));
            bool a10 = (tq1 == 0) ? (tk0 == 0) : ((tk0 == 0) || (ki0 <= qi1));
            bool a11 = (tq1 == 0) ? (tk1 == 0) : ((tk1 == 0) || (ki1 <= qi1));
            sc[nt][0] = fmaxf(sc[nt][0] * scale + (a00 ? 0.f : NEG) + pd0, -3.3e38f);
            sc[nt][1] = fmaxf(sc[nt][1] * scale + (a01 ? 0.f : NEG) + pd1, -3.3e38f);
            sc[nt][2] = fmaxf(sc[nt][2] * scale + (a10 ? 0.f : NEG) + pd0, -3.3e38f);
            sc[nt][3] = fmaxf(sc[nt][3] * scale + (a11 ? 0.f : NEG) + pd1, -3.3e38f);
            rx0 = fmaxf(rx0, fmaxf(sc[nt][0], sc[nt][1]));
            rx1 = fmaxf(rx1, fmaxf(sc[nt][2], sc[nt][3]));
        }
        rx0 = fmaxf(rx0, __shfl_xor_sync(0xffffffffu, rx0, 1));
        rx0 = fmaxf(rx0, __shfl_xor_sync(0xffffffffu, rx0, 2));
        rx1 = fmaxf(rx1, __shfl_xor_sync(0xffffffffu, rx1, 1));
        rx1 = fmaxf(rx1, __shfl_xor_sync(0xffffffffu, rx1, 2));

        float mn0 = fmaxf(m0, rx0), mn1 = fmaxf(m1, rx1);
        float corr0 = __expf(m0 - mn0), corr1 = __expf(m1 - mn1);

        // ---- exponentiate + row sums ----
        float rs0 = 0.f, rs1 = 0.f;
#pragma unroll
        for (int nt = 0; nt < 8; nt++) {
            sc[nt][0] = __expf(sc[nt][0] - mn0);
            sc[nt][1] = __expf(sc[nt][1] - mn0);
            sc[nt][2] = __expf(sc[nt][2] - mn1);
            sc[nt][3] = __expf(sc[nt][3] - mn1);
            rs0 += sc[nt][0] + sc[nt][1];
            rs1 += sc[nt][2] + sc[nt][3];
        }
        rs0 += __shfl_xor_sync(0xffffffffu, rs0, 1);
        rs0 += __shfl_xor_sync(0xffffffffu, rs0, 2);
        rs1 += __shfl_xor_sync(0xffffffffu, rs1, 1);
        rs1 += __shfl_xor_sync(0xffffffffu, rs1, 2);
        l0 = l0 * corr0 + rs0;
        l1 = l1 * corr1 + rs1;
        m0 = mn0; m1 = mn1;

        // ---- rescale O, pack P fragments (register-only), PV (ldmatrix) ----
#pragma unroll
        for (int dt = 0; dt < 8; dt++) {
            o[dt][0] *= corr0; o[dt][1] *= corr0;
            o[dt][2] *= corr1; o[dt][3] *= corr1;
        }
        uint32_t pf[4][4];
#pragma unroll
        for (int kc = 0; kc < 4; kc++) {
            pf[kc][0] = pack2(sc[2 * kc][0], sc[2 * kc][1]);
            pf[kc][1] = pack2(sc[2 * kc][2], sc[2 * kc][3]);
            pf[kc][2] = pack2(sc[2 * kc + 1][0], sc[2 * kc + 1][1]);
            pf[kc][3] = pack2(sc[2 * kc + 1][2], sc[2 * kc + 1][3]);
        }
#pragma unroll
        for (int kc = 0; kc < 4; kc++) {
            uint32_t ko = kc * 32;
            uint32_t vq[4][4];
#pragma unroll
            for (int j = 0; j < 4; j++)
                ldsm4(vq[j], vsb + lboff[j] + ko);
#pragma unroll
            for (int j = 0; j < 4; j++) {
                mma16(o[2 * j],     pf[kc], &vq[j][0]);
                mma16(o[2 * j + 1], pf[kc], &vq[j][2]);
            }
        }
    }

    // ---- epilogue ----
    float il0 = 1.0f / l0, il1 = 1.0f / l1;
    __half* r0p = out + (size_t)(bS + qi0) * QKD + h * 64;
    __half* r1p = out + (size_t)(bS + qi1) * QKD + h * 64;
#pragma unroll
    for (int dt = 0; dt < 8; dt++) {
        int d0 = dt * 8 + 2 * t4;
        *(__half2*)(r0p + d0) = __floats2half2_rn(o[dt][0] * il0, o[dt][1] * il0);
        *(__half2*)(r1p + d0) = __floats2half2_rn(o[dt][2] * il1, o[dt][3] * il1);
    }
}

// ---------------- host driver ----------------
extern "C" void kernel_launch(void* const* d_in, const int* in_sizes, int n_in,
                              void* d_out, int out_size) {
    const float* emb = (const float*)d_in[0];
    const int*   tt  = (const int*)  d_in[1];
    const float* am  = (const float*)d_in[2];
    const float* wq  = (const float*)d_in[3];
    const float* bq  = (const float*)d_in[4];
    const float* wk  = (const float*)d_in[5];
    const float* bk  = (const float*)d_in[6];
    const float* wv  = (const float*)d_in[7];
    const float* bv  = (const float*)d_in[8];
    const float* wo  = (const float*)d_in[9];
    const float* wg  = (const float*)d_in[10];
    const float* wu  = (const float*)d_in[11];
    const float* wd  = (const float*)d_in[12];
    const float* ln1 = (const float*)d_in[13];
    const float* ln2 = (const float*)d_in[14];
    const float* lnf = (const float*)d_in[15];

    float *x, *qkv, *bqkv;
    __half *h, *ao, *gt, *up, *wqkvT, *woT, *wgT, *wuT, *wdT;
    cudaGetSymbolAddress((void**)&x,   g_x);
    cudaGetSymbolAddress((void**)&h,   g_h);
    cudaGetSymbolAddress((void**)&qkv, g_qkv);
    cudaGetSymbolAddress((void**)&ao,  g_ao);
    cudaGetSymbolAddress((void**)&gt,  g_gate);
    cudaGetSymbolAddress((void**)&up,  g_up);
    cudaGetSymbolAddress((void**)&wqkvT, g_wqkvT);
    cudaGetSymbolAddress((void**)&woT, g_woT);
    cudaGetSymbolAddress((void**)&wgT, g_wgT);
    cudaGetSymbolAddress((void**)&wuT, g_wuT);
    cudaGetSymbolAddress((void**)&wdT, g_wdT);
    cudaGetSymbolAddress((void**)&bqkv, g_bqkv);

    const int GSMEM = 3 * 2 * STG_H * 2;   // 61440 bytes
    cudaFuncSetAttribute(mgemm_k<0, float>,  cudaFuncAttributeMaxDynamicSharedMemorySize, GSMEM);
    cudaFuncSetAttribute(mgemm_k<0, __half>, cudaFuncAttributeMaxDynamicSharedMemorySize, GSMEM);
    cudaFuncSetAttribute(mgemm_k<1, float>,  cudaFuncAttributeMaxDynamicSharedMemorySize, GSMEM);
    cudaFuncSetAttribute(mgemm_k<2, __half>, cudaFuncAttributeMaxDynamicSharedMemorySize, GSMEM);

    // weight transposes (+fp16 rounding); qkv packed into [q|k|v] rows
    size_t oLS = (size_t)QKVD * DM;
    transpose_k<<<dim3(QKD/32, DM/32, NL), 256>>>(wq, wqkvT,            DM, QKD, (size_t)DM*QKD, oLS);
    transpose_k<<<dim3(KVD/32, DM/32, NL), 256>>>(wk, wqkvT + (size_t)QKD*DM,       DM, KVD, (size_t)DM*KVD, oLS);
    transpose_k<<<dim3(KVD/32, DM/32, NL), 256>>>(wv, wqkvT + (size_t)(QKD+KVD)*DM, DM, KVD, (size_t)DM*KVD, oLS);
    transpose_k<<<dim3(DM/32, QKD/32, NL), 256>>>(wo, woT, QKD, DM, (size_t)QKD*DM, (size_t)DM*QKD);
    transpose_k<<<dim3(IFF/32, DM/32, NL), 256>>>(wg, wgT, DM, IFF, (size_t)DM*IFF, (size_t)IFF*DM);
    transpose_k<<<dim3(IFF/32, DM/32, NL), 256>>>(wu, wuT, DM, IFF, (size_t)DM*IFF, (size_t)IFF*DM);
    transpose_k<<<dim3(DM/32, IFF/32, NL), 256>>>(wd, wdT, IFF, DM, (size_t)IFF*DM, (size_t)DM*IFF);
    biaspack_k<<<(NL*QKVD + 255)/256, 256>>>(bq, bk, bv, bqkv);

    int nx = ROWS * DM;
    copy_k<<<(nx + 255) / 256, 256>>>(x, emb, nx);

    dim3 gQKV(QKVD / 128, ROWS / 128);   // (9, 32)
    dim3 gDM (DM   / 128, ROWS / 128);   // (7, 32)
    dim3 gFF (IFF  / 128, ROWS / 128);   // (38, 32)
    dim3 gAt (SEQ / 128, NHQ, BSZ);      // (16, 14, 2)

    for (int l = 0; l < NL; l++) {
        rmsnorm_k<__half><<<ROWS, 256>>>(x, ln1 + (size_t)l * DM, h);

        mgemm_k<0, float><<<gQKV, 256, GSMEM>>>(h, wqkvT + (size_t)l * QKVD * DM,
                                                bqkv + (size_t)l * QKVD, nullptr, qkv,
                                                ROWS, QKVD, DM);

        rope_k<<<ROWS, 16 * 32>>>(qkv);

        attn_k<<<gAt, 256>>>(qkv, tt, am, ao);

        mgemm_k<1, float><<<gDM, 256, GSMEM>>>(ao, woT + (size_t)l * DM * QKD,
                                               nullptr, nullptr, x, ROWS, DM, QKD);

        rmsnorm_k<__half><<<ROWS, 256>>>(x, ln2 + (size_t)l * DM, h);

        mgemm_k<0, __half><<<gFF, 256, GSMEM>>>(h, wgT + (size_t)l * IFF * DM,
                                                nullptr, nullptr, gt, ROWS, IFF, DM);
        mgemm_k<2, __half><<<gFF, 256, GSMEM>>>(h, wuT + (size_t)l * IFF * DM,
                                                nullptr, gt, up, ROWS, IFF, DM);
        mgemm_k<1, float><<<gDM, 256, GSMEM>>>(up, wdT + (size_t)l * DM * IFF,
                                               nullptr, nullptr, x, ROWS, DM, IFF);
    }

    rmsnorm_k<float><<<ROWS, 256>>>(x, lnf, (float*)d_out);
}

// round 13
// speedup vs baseline: 14.6427x; 1.0658x over previous
#include <cuda_runtime.h>
#include <cuda_fp16.h>
#include <math.h>
#include <stdint.h>

// Problem constants
#define BSZ 2
#define SEQ 2048
#define DM  896
#define NL  24
#define NHQ 14
#define NHKV 2
#define DH  64
#define IFF 4864
#define ROWS (BSZ*SEQ)          // 4096
#define QKD (NHQ*DH)            // 896
#define KVD (NHKV*DH)           // 128
#define QKVD (QKD + 2*KVD)      // 1152
#define NGU (2*IFF)             // 9728 (interleaved gate|up)

// ---------------- scratch (device globals; no allocations allowed) ----------
__device__ float  g_x  [ROWS*DM];
__device__ __half g_h  [ROWS*DM];
__device__ float  g_qkv[(size_t)ROWS*QKVD];
__device__ __half g_ao [ROWS*QKD];
__device__ __half g_up [(size_t)ROWS*IFF];
// transposed (K-major) weights in fp16
__device__ __half g_wqkvT[(size_t)NL*QKVD*DM];
__device__ __half g_woT  [(size_t)NL*DM*QKD];
__device__ __half g_wguT [(size_t)NL*NGU*DM];   // rows interleaved: 2j=gate, 2j+1=up
__device__ __half g_wdT  [(size_t)NL*DM*IFF];
__device__ float  g_bqkv [NL*QKVD];
// rope tables
__device__ float  g_rc[SEQ*32];
__device__ float  g_rs[SEQ*32];

// ---------------- PTX helpers ----------------
__device__ __forceinline__ uint32_t smem_u32(const void* p) {
    uint32_t a;
    asm("{ .reg .u64 t; cvta.to.shared.u64 t, %1; cvt.u32.u64 %0, t; }" : "=r"(a) : "l"(p));
    return a;
}
__device__ __forceinline__ void cp_async16(uint32_t s, const void* g) {
    asm volatile("cp.async.cg.shared.global [%0], [%1], 16;\n" :: "r"(s), "l"(g));
}
__device__ __forceinline__ void cp_commit() { asm volatile("cp.async.commit_group;\n" ::: "memory"); }
template <int N>
__device__ __forceinline__ void cp_wait() { asm volatile("cp.async.wait_group %0;\n" :: "n"(N) : "memory"); }

__device__ __forceinline__ void mma16(float* c, const uint32_t* a, const uint32_t* b) {
    asm volatile(
        "mma.sync.aligned.m16n8k16.row.col.f32.f16.f16.f32 "
        "{%0,%1,%2,%3}, {%4,%5,%6,%7}, {%8,%9}, {%0,%1,%2,%3};"
        : "+f"(c[0]), "+f"(c[1]), "+f"(c[2]), "+f"(c[3])
        : "r"(a[0]), "r"(a[1]), "r"(a[2]), "r"(a[3]), "r"(b[0]), "r"(b[1]));
}
__device__ __forceinline__ void ldsm4(uint32_t* r, uint32_t addr) {
    asm volatile("ldmatrix.sync.aligned.m8n8.x4.shared.b16 {%0,%1,%2,%3}, [%4];"
        : "=r"(r[0]), "=r"(r[1]), "=r"(r[2]), "=r"(r[3]) : "r"(addr));
}
__device__ __forceinline__ uint32_t pack2(float a, float b) {
    __half2 h = __floats2half2_rn(a, b);
    return *(uint32_t*)&h;
}

// ---------------- elementwise copy ----------------
__global__ void copy_k(float* __restrict__ dst, const float* __restrict__ src, int n) {
    int i = blockIdx.x * blockDim.x + threadIdx.x;
    if (i < n) dst[i] = src[i];
}

// ---------------- rope tables (same math as previous rope_k) ----------------
__global__ void ropetab_k(float* __restrict__ rc, float* __restrict__ rs) {
    int s = blockIdx.x, i = threadIdx.x;
    float inv = 1.0f / powf(1.0e6f, (float)i / 32.0f);
    float ang = (float)s * inv;
    rc[s * 32 + i] = cosf(ang);
    rs[s * 32 + i] = sinf(ang);
}

// ---------------- bias pack: [bq | bk | bv] per layer ----------------
__global__ void biaspack_k(const float* __restrict__ bq, const float* __restrict__ bk,
                           const float* __restrict__ bv, float* __restrict__ out) {
    int i = blockIdx.x * blockDim.x + threadIdx.x;
    if (i >= NL * QKVD) return;
    int l = i / QKVD, c = i % QKVD;
    float v;
    if (c < QKD) v = bq[l * QKD + c];
    else if (c < QKD + KVD) v = bk[l * KVD + c - QKD];
    else v = bv[l * KVD + c - QKD - KVD];
    out[i] = v;
}

// -------- transpose + fp16 round: out[z][rowMul*c+rowOff][r] = h(in[z][r][c])
__global__ __launch_bounds__(256) void transpose_k(const float* __restrict__ in,
                                                   __half* __restrict__ out,
                                                   int R, int C,
                                                   size_t inLS, size_t outLS,
                                                   int rowMul, int rowOff) {
    __shared__ float t[32][33];
    const float* ip = in + (size_t)blockIdx.z * inLS;
    __half* op = out + (size_t)blockIdx.z * outLS;
    int r0 = blockIdx.y * 32, c0 = blockIdx.x * 32;
    int tx = threadIdx.x & 31, ty = threadIdx.x >> 5;
#pragma unroll
    for (int i = 0; i < 32; i += 8)
        t[ty + i][tx] = ip[(size_t)(r0 + ty + i) * C + c0 + tx];
    __syncthreads();
#pragma unroll
    for (int i = 0; i < 32; i += 8)
        op[(size_t)((c0 + ty + i) * rowMul + rowOff) * R + r0 + tx] =
            __float2half_rn(t[tx][ty + i]);
}

// ---------------- RMSNorm (templated output type) ----------------
template <typename OT>
__global__ __launch_bounds__(256) void rmsnorm_k(const float* __restrict__ x,
                                                 const float* __restrict__ w,
                                                 OT* __restrict__ o) {
    int row = blockIdx.x;
    const float* xr = x + (size_t)row * DM;
    float s = 0.f;
    for (int i = threadIdx.x; i < DM; i += 256) { float v = xr[i]; s += v * v; }
    __shared__ float red[256];
    red[threadIdx.x] = s;
    __syncthreads();
    for (int st = 128; st > 0; st >>= 1) {
        if (threadIdx.x < st) red[threadIdx.x] += red[threadIdx.x + st];
        __syncthreads();
    }
    float r = rsqrtf(red[0] / (float)DM + 1e-6f);
    OT* orow = o + (size_t)row * DM;
    for (int i = threadIdx.x; i < DM; i += 256) {
        float v = xr[i] * r * w[i];
        orow[i] = (OT)v;
    }
}

// ---------------- fp16 mma GEMM: C[M,N] = A[M,K] @ Bt[N,K]^T ----------------
// EPI 0: C = acc + bias ; EPI 1: C(f32) += acc ;
// EPI 3: Bt rows interleave gate/up -> C(f16)[r][cg/2] = h(silu(v0)*v1)
#define PH 40                     // halves per smem row
#define STG_H (128 * PH)          // halves per A (or B) stage
template <int EPI, typename CT>
__global__ __launch_bounds__(256, 2) void mgemm_k(const __half* __restrict__ A,
                                                  const __half* __restrict__ Bt,
                                                  const float* __restrict__ bias,
                                                  CT* __restrict__ C,
                                                  int M, int N, int K) {
    extern __shared__ __half smemh[];
    uint32_t sbase = smem_u32(smemh);

    int tid = threadIdx.x;
    int wid = tid >> 5;
    int lane = tid & 31;
    int gid = lane >> 2, t4 = lane & 3;
    int wm = wid & 1, wn = wid >> 1;
    int row0 = blockIdx.y * 128, col0 = blockIdx.x * 128;

    const int NK = K >> 5;
    float acc[4][4][4] = {};

    // ldmatrix lane offsets (bytes)
    uint32_t aoff[4];
#pragma unroll
    for (int mt = 0; mt < 4; mt++)
        aoff[mt] = (uint32_t)(((wm * 64 + mt * 16 + (lane & 15)) * PH
                               + ((lane >> 4) * 8)) * 2);
    uint32_t boff[2];
#pragma unroll
    for (int j = 0; j < 2; j++)
        boff[j] = (uint32_t)(((wn * 32 + j * 16 + (lane & 7) + ((lane & 16) ? 8 : 0)) * PH
                              + (((lane >> 3) & 1) * 8)) * 2);

    // cp.async load coords
    int lr = tid >> 2, lc = tid & 3;
    uint32_t loff = (uint32_t)(lr * PH + lc * 8) * 2;
    const __half* Ag  = A  + (size_t)(row0 + lr) * K + lc * 8;
    const __half* Bg  = Bt + (size_t)(col0 + lr) * K + lc * 8;
    const __half* Ag2 = Ag + 64 * K;
    const __half* Bg2 = Bg + 64 * K;
    uint32_t loff2 = loff + (uint32_t)(64 * PH) * 2;

#define PREFETCH(stg, k0)                                             \
    do {                                                              \
        uint32_t sa = sbase + (stg) * (2 * STG_H * 2);                \
        uint32_t sb = sa + STG_H * 2;                                 \
        cp_async16(sa + loff,  Ag  + (k0));                           \
        cp_async16(sa + loff2, Ag2 + (k0));                           \
        cp_async16(sb + loff,  Bg  + (k0));                           \
        cp_async16(sb + loff2, Bg2 + (k0));                           \
    } while (0)

    PREFETCH(0, 0);  cp_commit();
    PREFETCH(1, 32); cp_commit();
    PREFETCH(2, 64); cp_commit();

    for (int kt = 0; kt < NK; kt++) {
        if (kt + 3 < NK) cp_wait<2>(); else cp_wait<0>();
        __syncthreads();
        if (kt + 3 < NK) {
            PREFETCH((kt + 3) & 3, (kt + 3) << 5);
            cp_commit();
        }
        int s = kt & 3;
        uint32_t sa = sbase + s * (2 * STG_H * 2);
        uint32_t sb = sa + STG_H * 2;
#pragma unroll
        for (int ks = 0; ks < 2; ks++) {
            uint32_t ko = ks * 32;   // 16 halves
            uint32_t af[4][4];
#pragma unroll
            for (int mt = 0; mt < 4; mt++)
                ldsm4(af[mt], sa + aoff[mt] + ko);
            uint32_t bq0[4], bq1[4];
            ldsm4(bq0, sb + boff[0] + ko);
            ldsm4(bq1, sb + boff[1] + ko);
#pragma unroll
            for (int mt = 0; mt < 4; mt++) {
                mma16(acc[mt][0], af[mt], &bq0[0]);
                mma16(acc[mt][1], af[mt], &bq0[2]);
                mma16(acc[mt][2], af[mt], &bq1[0]);
                mma16(acc[mt][3], af[mt], &bq1[2]);
            }
        }
    }
#undef PREFETCH

#pragma unroll
    for (int mt = 0; mt < 4; mt++) {
#pragma unroll
        for (int nt = 0; nt < 4; nt++) {
            int rg = row0 + wm * 64 + mt * 16 + gid;
            int cg = col0 + wn * 32 + nt * 8 + 2 * t4;
#pragma unroll
            for (int half = 0; half < 2; half++) {
                int r = rg + half * 8;
                float v0 = acc[mt][nt][half * 2 + 0];
                float v1 = acc[mt][nt][half * 2 + 1];
                if (EPI == 0) {
                    size_t idx = (size_t)r * N + cg;
                    float b0 = bias ? bias[cg] : 0.f;
                    float b1 = bias ? bias[cg + 1] : 0.f;
                    if (sizeof(CT) == 2) {
                        __half2 hv = __floats2half2_rn(v0 + b0, v1 + b1);
                        *(__half2*)((__half*)C + idx) = hv;
                    } else {
                        *(float2*)((float*)C + idx) = make_float2(v0 + b0, v1 + b1);
                    }
                } else if (EPI == 1) {
                    size_t idx = (size_t)r * N + cg;
                    float2 o = *(float2*)((float*)C + idx);
                    o.x += v0; o.y += v1;
                    *(float2*)((float*)C + idx) = o;
                } else {
                    // EPI 3: v0=gate, v1=up -> one fp16 output at column cg/2
                    size_t idx = (size_t)r * (N >> 1) + (cg >> 1);
                    float gv = v0 * (1.f / (1.f + expf(-v0))) * v1;
                    ((__half*)C)[idx] = __float2half_rn(gv);
                }
            }
        }
    }
}

// ---------------- Attention: FA2 tensor-core kernel, rope fused -------------
// 256 threads (8 warps), 128 queries/block (16/warp), K-tile 64.
// grid (SEQ/128, NHQ, BSZ).
#define PKH 72
__global__ __launch_bounds__(256) void attn_k(const float* __restrict__ qkv,
                                              const int* __restrict__ tt,
                                              const float* __restrict__ am,
                                              const float* __restrict__ rc,
                                              const float* __restrict__ rs,
                                              __half* __restrict__ out) {
    __shared__ __half Ks [64][PKH];     // [key][d]
    __shared__ __half VsT[64][PKH];     // [d][key]
    __shared__ __half qsh[128][PKH];    // [q][d]
    __shared__ int    tts[64];
    __shared__ float  padf[64];

    int b = blockIdx.z, h = blockIdx.y;
    int tid = threadIdx.x;
    int w = tid >> 5;
    int lane = tid & 31;
    int gid = lane >> 2, t4 = lane & 3;
    int qt0 = blockIdx.x * 128;
    int kvh = h / (NHQ / NHKV);
    int bS = b * SEQ;
    const float NEG = -3.0e38f;
    const float scale = 0.125f;

    uint32_t ksb = smem_u32(&Ks[0][0]);
    uint32_t vsb = smem_u32(&VsT[0][0]);
    uint32_t lboff[4];
#pragma unroll
    for (int j = 0; j < 4; j++)
        lboff[j] = (uint32_t)(((j * 16 + (lane & 7) + ((lane & 16) ? 8 : 0)) * PKH
                               + (((lane >> 3) & 1) * 8)) * 2);

    // ---- load Q tile with fused rope (fp32 math -> fp16 smem) ----
    for (int idx = tid; idx < 128 * 8; idx += 256) {
        int r = idx >> 3, c4 = (idx & 7) * 4;      // c4 in [0,28]
        int s = qt0 + r;
        const float* qb_ = qkv + (size_t)(bS + s) * QKVD + h * 64;
        float4 qa = *(const float4*)(qb_ + c4);
        float4 qc = *(const float4*)(qb_ + c4 + 32);
        float4 cs = *(const float4*)(rc + s * 32 + c4);
        float4 sn = *(const float4*)(rs + s * 32 + c4);
        *(__half2*)&qsh[r][c4]          = __floats2half2_rn(qa.x*cs.x - qc.x*sn.x, qa.y*cs.y - qc.y*sn.y);
        *(__half2*)&qsh[r][c4 + 2]      = __floats2half2_rn(qa.z*cs.z - qc.z*sn.z, qa.w*cs.w - qc.w*sn.w);
        *(__half2*)&qsh[r][c4 + 32]     = __floats2half2_rn(qc.x*cs.x + qa.x*sn.x, qc.y*cs.y + qa.y*sn.y);
        *(__half2*)&qsh[r][c4 + 34]     = __floats2half2_rn(qc.z*cs.z + qa.z*sn.z, qc.w*cs.w + qa.w*sn.w);
    }
    __syncthreads();

    // ---- Q fragments in registers ----
    int qb = w * 16;
    uint32_t qf[4][4];
#pragma unroll
    for (int kc = 0; kc < 4; kc++) {
        int k0 = kc * 16 + 2 * t4;
        qf[kc][0] = *(const uint32_t*)&qsh[qb + gid][k0];
        qf[kc][1] = *(const uint32_t*)&qsh[qb + gid + 8][k0];
        qf[kc][2] = *(const uint32_t*)&qsh[qb + gid][k0 + 8];
        qf[kc][3] = *(const uint32_t*)&qsh[qb + gid + 8][k0 + 8];
    }

    int qi0 = qt0 + qb + gid, qi1 = qi0 + 8;
    int tq0 = tt[bS + qi0], tq1 = tt[bS + qi1];

    float m0 = -INFINITY, m1 = -INFINITY, l0 = 0.f, l1 = 0.f;
    float o[8][4];
#pragma unroll
    for (int dt = 0; dt < 8; dt++) { o[dt][0] = 0.f; o[dt][1] = 0.f; o[dt][2] = 0.f; o[dt][3] = 0.f; }

    for (int kt = 0; kt < SEQ; kt += 64) {
        __syncthreads();
        // K tile with fused rope: [key][d] fp16
        for (int idx = tid; idx < 64 * 8; idx += 256) {
            int r = idx >> 3, c4 = (idx & 7) * 4;
            int s = kt + r;
            const float* kb_ = qkv + (size_t)(bS + s) * QKVD + QKD + kvh * 64;
            float4 ka = *(const float4*)(kb_ + c4);
            float4 kc_ = *(const float4*)(kb_ + c4 + 32);
            float4 cs = *(const float4*)(rc + s * 32 + c4);
            float4 sn = *(const float4*)(rs + s * 32 + c4);
            *(__half2*)&Ks[r][c4]      = __floats2half2_rn(ka.x*cs.x - kc_.x*sn.x, ka.y*cs.y - kc_.y*sn.y);
            *(__half2*)&Ks[r][c4 + 2]  = __floats2half2_rn(ka.z*cs.z - kc_.z*sn.z, ka.w*cs.w - kc_.w*sn.w);
            *(__half2*)&Ks[r][c4 + 32] = __floats2half2_rn(kc_.x*cs.x + ka.x*sn.x, kc_.y*cs.y + ka.y*sn.y);
            *(__half2*)&Ks[r][c4 + 34] = __floats2half2_rn(kc_.z*cs.z + ka.z*sn.z, kc_.w*cs.w + ka.w*sn.w);
        }
        // V tile transposed: [d][key] fp16, key-pairs packed as half2
        for (int idx = tid; idx < 32 * 16; idx += 256) {
            int rp = idx >> 4, c4 = (idx & 15) * 4;
            int r = rp * 2;
            const float* vb = qkv + (size_t)(bS + kt + r) * QKVD + QKD + KVD + kvh * 64;
            float4 va = *(const float4*)(vb + c4);
            float4 vc = *(const float4*)(vb + QKVD + c4);
            *(__half2*)&VsT[c4 + 0][r] = __floats2half2_rn(va.x, vc.x);
            *(__half2*)&VsT[c4 + 1][r] = __floats2half2_rn(va.y, vc.y);
            *(__half2*)&VsT[c4 + 2][r] = __floats2half2_rn(va.z, vc.z);
            *(__half2*)&VsT[c4 + 3][r] = __floats2half2_rn(va.w, vc.w);
        }
        if (tid < 64) {
            tts[tid]  = tt[bS + kt + tid];
            padf[tid] = (1.f - am[bS + kt + tid]) * NEG;
        }
        __syncthreads();

        // ---- QK^T (ldmatrix) ----
        float sc[8][4];
#pragma unroll
        for (int nt = 0; nt < 8; nt++) { sc[nt][0] = 0.f; sc[nt][1] = 0.f; sc[nt][2] = 0.f; sc[nt][3] = 0.f; }
#pragma unroll
        for (int kc = 0; kc < 4; kc++) {
            uint32_t ko = kc * 32;
            uint32_t kq[4][4];
#pragma unroll
            for (int j = 0; j < 4; j++)
                ldsm4(kq[j], ksb + lboff[j] + ko);
#pragma unroll
            for (int j = 0; j < 4; j++) {
                mma16(sc[2 * j],     qf[kc], &kq[j][0]);
                mma16(sc[2 * j + 1], qf[kc], &kq[j][2]);
            }
        }

        // ---- mask + bias + row max ----
        float rx0 = -INFINITY, rx1 = -INFINITY;
#pragma unroll
        for (int nt = 0; nt < 8; nt++) {
            int c0 = nt * 8 + 2 * t4, c1 = c0 + 1;
            int tk0 = tts[c0], tk1 = tts[c1];
            float pd0 = padf[c0], pd1 = padf[c1];
            int ki0 = kt + c0, ki1 = kt + c1;
            bool a00 = (tq0 == 0) ? (tk0 == 0) : ((tk0 == 0) || (ki0 <= qi0));
            bool a01 = (tq0 == 0) ? (tk1 == 0) : ((tk1 == 0) || (ki1 <= qi0));
            bool a10 = (tq1 == 0) ? (tk0 == 0) : ((tk0 == 0) || (ki0 <= qi1));
            bool a11 = (tq1 == 0) ? (tk1 == 0) : ((tk1 == 0) || (ki1 <= qi1));
            sc[nt][0] = fmaxf(sc[nt][0] * scale + (a00 ? 0.f : NEG) + pd0, -3.3e38f);
            sc[nt][1] = fmaxf(sc[nt][1] * scale + (a01 ? 0.f : NEG) + pd1, -3.3e38f);
            sc[nt][2] = fmaxf(sc[nt][2] * scale + (a10 ? 0.f : NEG) + pd0, -3.3e38f);
            sc[nt][3] = fmaxf(sc[nt][3] * scale + (a11 ? 0.f : NEG) + pd1, -3.3e38f);
            rx0 = fmaxf(rx0, fmaxf(sc[nt][0], sc[nt][1]));
            rx1 = fmaxf(rx1, fmaxf(sc[nt][2], sc[nt][3]));
        }
        rx0 = fmaxf(rx0, __shfl_xor_sync(0xffffffffu, rx0, 1));
        rx0 = fmaxf(rx0, __shfl_xor_sync(0xffffffffu, rx0, 2));
        rx1 = fmaxf(rx1, __shfl_xor_sync(0xffffffffu, rx1, 1));
        rx1 = fmaxf(rx1, __shfl_xor_sync(0xffffffffu, rx1, 2));

        float mn0 = fmaxf(m0, rx0), mn1 = fmaxf(m1, rx1);
        float corr0 = __expf(m0 - mn0), corr1 = __expf(m1 - mn1);

        // ---- exponentiate + row sums ----
        float rs0 = 0.f, rs1 = 0.f;
#pragma unroll
        for (int nt = 0; nt < 8; nt++) {
            sc[nt][0] = __expf(sc[nt][0] - mn0);
            sc[nt][1] = __expf(sc[nt][1] - mn0);
            sc[nt][2] = __expf(sc[nt][2] - mn1);
            sc[nt][3] = __expf(sc[nt][3] - mn1);
            rs0 += sc[nt][0] + sc[nt][1];
            rs1 += sc[nt][2] + sc[nt][3];
        }
        rs0 += __shfl_xor_sync(0xffffffffu, rs0, 1);
        rs0 += __shfl_xor_sync(0xffffffffu, rs0, 2);
        rs1 += __shfl_xor_sync(0xffffffffu, rs1, 1);
        rs1 += __shfl_xor_sync(0xffffffffu, rs1, 2);
        l0 = l0 * corr0 + rs0;
        l1 = l1 * corr1 + rs1;
        m0 = mn0; m1 = mn1;

        // ---- rescale O, pack P fragments, PV (ldmatrix) ----
#pragma unroll
        for (int dt = 0; dt < 8; dt++) {
            o[dt][0] *= corr0; o[dt][1] *= corr0;
            o[dt][2] *= corr1; o[dt][3] *= corr1;
        }
        uint32_t pf[4][4];
#pragma unroll
        for (int kc = 0; kc < 4; kc++) {
            pf[kc][0] = pack2(sc[2 * kc][0], sc[2 * kc][1]);
            pf[kc][1] = pack2(sc[2 * kc][2], sc[2 * kc][3]);
            pf[kc][2] = pack2(sc[2 * kc + 1][0], sc[2 * kc + 1][1]);
            pf[kc][3] = pack2(sc[2 * kc + 1][2], sc[2 * kc + 1][3]);
        }
#pragma unroll
        for (int kc = 0; kc < 4; kc++) {
            uint32_t ko = kc * 32;
            uint32_t vq[4][4];
#pragma unroll
            for (int j = 0; j < 4; j++)
                ldsm4(vq[j], vsb + lboff[j] + ko);
#pragma unroll
            for (int j = 0; j < 4; j++) {
                mma16(o[2 * j],     pf[kc], &vq[j][0]);
                mma16(o[2 * j + 1], pf[kc], &vq[j][2]);
            }
        }
    }

    // ---- epilogue ----
    float il0 = 1.0f / l0, il1 = 1.0f / l1;
    __half* r0p = out + (size_t)(bS + qi0) * QKD + h * 64;
    __half* r1p = out + (size_t)(bS + qi1) * QKD + h * 64;
#pragma unroll
    for (int dt = 0; dt < 8; dt++) {
        int d0 = dt * 8 + 2 * t4;
        *(__half2*)(r0p + d0) = __floats2half2_rn(o[dt][0] * il0, o[dt][1] * il0);
        *(__half2*)(r1p + d0) = __floats2half2_rn(o[dt][2] * il1, o[dt][3] * il1);
    }
}

// ---------------- host driver ----------------
extern "C" void kernel_launch(void* const* d_in, const int* in_sizes, int n_in,
                              void* d_out, int out_size) {
    const float* emb = (const float*)d_in[0];
    const int*   tt  = (const int*)  d_in[1];
    const float* am  = (const float*)d_in[2];
    const float* wq  = (const float*)d_in[3];
    const float* bq  = (const float*)d_in[4];
    const float* wk  = (const float*)d_in[5];
    const float* bk  = (const float*)d_in[6];
    const float* wv  = (const float*)d_in[7];
    const float* bv  = (const float*)d_in[8];
    const float* wo  = (const float*)d_in[9];
    const float* wg  = (const float*)d_in[10];
    const float* wu  = (const float*)d_in[11];
    const float* wd  = (const float*)d_in[12];
    const float* ln1 = (const float*)d_in[13];
    const float* ln2 = (const float*)d_in[14];
    const float* lnf = (const float*)d_in[15];

    float *x, *qkv, *bqkv, *rc, *rs;
    __half *h, *ao, *up, *wqkvT, *woT, *wguT, *wdT;
    cudaGetSymbolAddress((void**)&x,   g_x);
    cudaGetSymbolAddress((void**)&h,   g_h);
    cudaGetSymbolAddress((void**)&qkv, g_qkv);
    cudaGetSymbolAddress((void**)&ao,  g_ao);
    cudaGetSymbolAddress((void**)&up,  g_up);
    cudaGetSymbolAddress((void**)&wqkvT, g_wqkvT);
    cudaGetSymbolAddress((void**)&woT, g_woT);
    cudaGetSymbolAddress((void**)&wguT, g_wguT);
    cudaGetSymbolAddress((void**)&wdT, g_wdT);
    cudaGetSymbolAddress((void**)&bqkv, g_bqkv);
    cudaGetSymbolAddress((void**)&rc, g_rc);
    cudaGetSymbolAddress((void**)&rs, g_rs);

    const int GSMEM = 4 * 2 * STG_H * 2;   // 81920 bytes
    cudaFuncSetAttribute(mgemm_k<0, float>,  cudaFuncAttributeMaxDynamicSharedMemorySize, GSMEM);
    cudaFuncSetAttribute(mgemm_k<1, float>,  cudaFuncAttributeMaxDynamicSharedMemorySize, GSMEM);
    cudaFuncSetAttribute(mgemm_k<3, __half>, cudaFuncAttributeMaxDynamicSharedMemorySize, GSMEM);

    // weight transposes (+fp16 rounding)
    size_t oLS = (size_t)QKVD * DM;
    transpose_k<<<dim3(QKD/32, DM/32, NL), 256>>>(wq, wqkvT,            DM, QKD, (size_t)DM*QKD, oLS, 1, 0);
    transpose_k<<<dim3(KVD/32, DM/32, NL), 256>>>(wk, wqkvT + (size_t)QKD*DM,       DM, KVD, (size_t)DM*KVD, oLS, 1, 0);
    transpose_k<<<dim3(KVD/32, DM/32, NL), 256>>>(wv, wqkvT + (size_t)(QKD+KVD)*DM, DM, KVD, (size_t)DM*KVD, oLS, 1, 0);
    transpose_k<<<dim3(DM/32, QKD/32, NL), 256>>>(wo, woT, QKD, DM, (size_t)QKD*DM, (size_t)DM*QKD, 1, 0);
    // gate/up interleaved: rows 2j / 2j+1
    transpose_k<<<dim3(IFF/32, DM/32, NL), 256>>>(wg, wguT, DM, IFF, (size_t)DM*IFF, (size_t)NGU*DM, 2, 0);
    transpose_k<<<dim3(IFF/32, DM/32, NL), 256>>>(wu, wguT, DM, IFF, (size_t)DM*IFF, (size_t)NGU*DM, 2, 1);
    transpose_k<<<dim3(DM/32, IFF/32, NL), 256>>>(wd, wdT, IFF, DM, (size_t)IFF*DM, (size_t)DM*IFF, 1, 0);
    biaspack_k<<<(NL*QKVD + 255)/256, 256>>>(bq, bk, bv, bqkv);
    ropetab_k<<<SEQ, 32>>>(rc, rs);

    int nx = ROWS * DM;
    copy_k<<<(nx + 255) / 256, 256>>>(x, emb, nx);

    dim3 gQKV(QKVD / 128, ROWS / 128);   // (9, 32)
    dim3 gDM (DM   / 128, ROWS / 128);   // (7, 32)
    dim3 gGU (NGU  / 128, ROWS / 128);   // (76, 32)
    dim3 gAt (SEQ / 128, NHQ, BSZ);      // (16, 14, 2)

    for (int l = 0; l < NL; l++) {
        rmsnorm_k<__half><<<ROWS, 256>>>(x, ln1 + (size_t)l * DM, h);

        mgemm_k<0, float><<<gQKV, 256, GSMEM>>>(h, wqkvT + (size_t)l * QKVD * DM,
                                                bqkv + (size_t)l * QKVD, qkv,
                                                ROWS, QKVD, DM);

        attn_k<<<gAt, 256>>>(qkv, tt, am, rc, rs, ao);

        mgemm_k<1, float><<<gDM, 256, GSMEM>>>(ao, woT + (size_t)l * DM * QKD,
                                               nullptr, x, ROWS, DM, QKD);

        rmsnorm_k<__half><<<ROWS, 256>>>(x, ln2 + (size_t)l * DM, h);

        mgemm_k<3, __half><<<gGU, 256, GSMEM>>>(h, wguT + (size_t)l * NGU * DM,
                                                nullptr, up, ROWS, NGU, DM);
        mgemm_k<1, float><<<gDM, 256, GSMEM>>>(up, wdT + (size_t)l * DM * IFF,
                                               nullptr, x, ROWS, DM, IFF);
    }

    rmsnorm_k<float><<<ROWS, 256>>>(x, lnf, (float*)d_out);
}